// round 7
// baseline (speedup 1.0000x reference)
#include <cuda_runtime.h>
#include <stdint.h>
#include <math.h>

// LocalRNN: B=16, L=1024, D=256, ksize=16
#define B_   16
#define L_   1024
#define D_   256
#define KS_  16
#define G_   768
#define NCH_ (B_ * L_)

// Static device scratch
__device__ float    g_gi[(size_t)NCH_ * G_];          // gi[chain][gate_dim]
__device__ uint32_t g_wt2[196608];                    // W_hh tf32, mma-fragment order
__device__ float    g_hnew[(size_t)128 * 128 * D_];   // per-CTA new-h scratch

__device__ __forceinline__ float fsig(float x)   { return __fdividef(1.f, 1.f + __expf(-x)); }
__device__ __forceinline__ float ftanhf(float x) { return __fdividef(2.f, 1.f + __expf(-2.f * x)) - 1.f; }
__device__ __forceinline__ uint32_t tf32_of(float f) {
    uint32_t v; asm("cvt.rna.tf32.f32 %0, %1;" : "=r"(v) : "f"(f)); return v;
}
// paired-k permutation: (k, k+4) adjacent within each 8-group
__device__ __forceinline__ int permk(int k) {
    return (k & ~7) + ((k & 3) << 1) + ((k >> 2) & 1);
}
__device__ __forceinline__ void mma8(float* d, const uint32_t* a, uint32_t b0, uint32_t b1) {
    asm volatile(
        "mma.sync.aligned.m16n8k8.row.col.f32.tf32.tf32.f32 "
        "{%0,%1,%2,%3}, {%4,%5,%6,%7}, {%8,%9}, {%0,%1,%2,%3};"
        : "+f"(d[0]), "+f"(d[1]), "+f"(d[2]), "+f"(d[3])
        : "r"(a[0]), "r"(a[1]), "r"(a[2]), "r"(a[3]), "r"(b0), "r"(b1));
}
__device__ __forceinline__ uint32_t smem_u32(const void* p) {
    uint32_t a;
    asm("{ .reg .u64 t; cvta.to.shared.u64 t, %1; cvt.u32.u64 %0, t; }" : "=r"(a) : "l"(p));
    return a;
}
__device__ __forceinline__ void cp16(uint32_t dst, const void* src) {
    asm volatile("cp.async.ca.shared.global [%0], [%1], 16;" :: "r"(dst), "l"(src) : "memory");
}
#define CP_COMMIT() asm volatile("cp.async.commit_group;" ::: "memory")
#define CP_WAIT2()  asm volatile("cp.async.wait_group 2;" ::: "memory")
#define CP_WAIT0()  asm volatile("cp.async.wait_group 0;" ::: "memory")

// ---------------------------------------------------------------------------
// Prep: W_hh -> tf32 in mma-fragment order.
// word index w in slab: ((((ncol*8+k8)*3+g)*2+nt)*32+lane)*2+r, slab = c*4+kq
// maps to W_hh[g*256 + ncol*128 + c*16 + nt*8 + (lane>>2)][kq*64+k8*8+(lane&3)+r*4]
// ---------------------------------------------------------------------------
__global__ void wprep_kernel(const float* __restrict__ Whh) {
    int e = blockIdx.x * 256 + threadIdx.x;
    if (e >= 196608) return;
    int slab = e / 6144, w = e % 6144;
    int c8 = slab >> 2, kq = slab & 3;
    int r = w & 1, lane = (w >> 1) & 31;
    int u = w >> 6;
    int nt = u & 1;
    int v = u >> 1;
    int g = v % 3, m = v / 3;
    int k8 = m & 7, ncol = m >> 3;
    int qcol = lane & 3, qrow = lane >> 2;
    int k   = kq * 64 + k8 * 8 + qcol + r * 4;
    int dim = ncol * 128 + c8 * 16 + nt * 8 + qrow;
    g_wt2[e] = tf32_of(Whh[(size_t)(g * 256 + dim) * D_ + k]);
}

// ---------------------------------------------------------------------------
// gi = x @ W_ih^T + b_ih via tf32 mma. grid (128, 6), 256 thr.
// CTA tile: 128 chains x 128 gate-dims, K=256 in 4 chunks of 64.
// Smem: Xs[128][72] (paired-k), Wst[64][136] ([k][gd]).
// ---------------------------------------------------------------------------
#define GX_S 72
#define GW_S 136
#define GI_SMEM_BYTES ((128 * GX_S + 64 * GW_S) * 4)

__global__ __launch_bounds__(256) void gi_mma_kernel(
    const float* __restrict__ x,
    const float* __restrict__ Wih,
    const float* __restrict__ bih)
{
    extern __shared__ uint32_t gsm[];
    uint32_t* Xs  = gsm;
    uint32_t* Wst = gsm + 128 * GX_S;

    const int tid = threadIdx.x;
    const int lane = tid & 31, wid = tid >> 5;
    const int qrow = lane >> 2, qcol = lane & 3;
    const int mbase = (wid & 3) * 32;
    const int ncol  = wid >> 2;
    const int mt0 = blockIdx.x * 128;
    const int ntile = blockIdx.y * 128;

    float acc[2][8][4];
#pragma unroll
    for (int mt = 0; mt < 2; mt++)
#pragma unroll
        for (int nt = 0; nt < 8; nt++)
#pragma unroll
            for (int e = 0; e < 4; e++) acc[mt][nt][e] = 0.f;

    for (int kq = 0; kq < 4; kq++) {
        __syncthreads();
        {   // stage x tile (paired-k layout)
            const int row = tid >> 1, half = tid & 1;
            const float* xp = x + (size_t)(mt0 + row) * D_ + kq * 64 + half * 32;
#pragma unroll
            for (int i = 0; i < 4; i++) {
                float4 v0 = *(const float4*)(xp + i * 8);
                float4 v1 = *(const float4*)(xp + i * 8 + 4);
                uint32_t* d = Xs + row * GX_S + half * 32 + i * 8;
                d[0] = tf32_of(v0.x); d[1] = tf32_of(v1.x);
                d[2] = tf32_of(v0.y); d[3] = tf32_of(v1.y);
                d[4] = tf32_of(v0.z); d[5] = tf32_of(v1.z);
                d[6] = tf32_of(v0.w); d[7] = tf32_of(v1.w);
            }
        }
        {   // stage Wih tile transposed: Wst[k][gd]
            const int gd = tid >> 1, half = tid & 1;
            const float* wp = Wih + (size_t)(ntile + gd) * D_ + kq * 64 + half * 32;
#pragma unroll
            for (int i = 0; i < 8; i++) {
                float4 v = *(const float4*)(wp + i * 4);
                int kk = half * 32 + i * 4;
                Wst[(kk + 0) * GW_S + gd] = tf32_of(v.x);
                Wst[(kk + 1) * GW_S + gd] = tf32_of(v.y);
                Wst[(kk + 2) * GW_S + gd] = tf32_of(v.z);
                Wst[(kk + 3) * GW_S + gd] = tf32_of(v.w);
            }
        }
        __syncthreads();

#pragma unroll
        for (int k8 = 0; k8 < 8; k8++) {
            uint32_t a[2][4];
#pragma unroll
            for (int mt = 0; mt < 2; mt++) {
                const int r = mbase + mt * 16 + qrow;
                uint2 lo = *(const uint2*)(Xs + r * GX_S + k8 * 8 + qcol * 2);
                uint2 hi = *(const uint2*)(Xs + (r + 8) * GX_S + k8 * 8 + qcol * 2);
                a[mt][0] = lo.x; a[mt][2] = lo.y;
                a[mt][1] = hi.x; a[mt][3] = hi.y;
            }
            const uint32_t* wb = Wst + (k8 * 8 + qcol) * GW_S + ncol * 64 + qrow;
#pragma unroll
            for (int nt = 0; nt < 8; nt++) {
                uint32_t b0 = wb[nt * 8];
                uint32_t b1 = wb[4 * GW_S + nt * 8];
                mma8(acc[0][nt], a[0], b0, b1);
                mma8(acc[1][nt], a[1], b0, b1);
            }
        }
    }

#pragma unroll
    for (int nt = 0; nt < 8; nt++) {
        const int gd = ntile + ncol * 64 + nt * 8 + 2 * qcol;
        const float2 bv = *(const float2*)(bih + gd);
#pragma unroll
        for (int mt = 0; mt < 2; mt++)
#pragma unroll
            for (int eh = 0; eh < 2; eh++) {
                const int chain = mt0 + mbase + mt * 16 + eh * 8 + qrow;
                float2 o;
                o.x = acc[mt][nt][eh * 2 + 0] + bv.x;
                o.y = acc[mt][nt][eh * 2 + 1] + bv.y;
                *(float2*)(g_gi + (size_t)chain * G_ + gd) = o;
            }
    }
}

// ---------------------------------------------------------------------------
// Main recurrence. 128 CTAs x 128 chains, 8 warps (4M x 2N-col).
// Smem floats: Hs[128][264] @0 | Ws ring 3x6144 @33792 | bih @52224 | bhh @52992
// Per step: 8 chunks (16 dims per warp-col) x 4 kq slabs; slabs cp.async-
// prefetched 3 deep from fragment-ordered g_wt2; fused GRU epilogue.
// ---------------------------------------------------------------------------
#define HS_S   264
#define SLAB_W 6144
#define SMF_WS  (128 * HS_S)            // 33792
#define SMF_BIH (SMF_WS + 3 * SLAB_W)   // 52224
#define SMF_BHH (SMF_BIH + G_)
#define RNN_SMEM_BYTES ((SMF_BHH + G_) * 4)

__global__ __launch_bounds__(256, 1) void rnn_mma_kernel(
    const float* __restrict__ bih_g,
    const float* __restrict__ bhh_g,
    float* __restrict__ out)
{
    extern __shared__ uint32_t sm[];
    uint32_t* Hs_u  = sm;
    float*    Hs_f  = (float*)sm;
    uint32_t* Ws_u  = sm + SMF_WS;
    float*    bih_s = (float*)(sm + SMF_BIH);
    float*    bhh_s = (float*)(sm + SMF_BHH);
    const uint32_t ws_b = smem_u32(Ws_u);

    const int tid = threadIdx.x;
    const int lane = tid & 31, wid = tid >> 5;
    const int qrow = lane >> 2, qcol = lane & 3;
    const int mbase = (wid & 3) * 32;
    const int ncol  = wid >> 2;
    const int n0 = blockIdx.x * 128;

    // kick off first 3 slab prefetches
#pragma unroll
    for (int p = 0; p < 3; p++) {
        const uint4* src = ((const uint4*)g_wt2) + (size_t)p * (SLAB_W / 4);
        uint32_t dst = ws_b + p * SLAB_W * 4;
#pragma unroll
        for (int j = 0; j < 6; j++)
            cp16(dst + (tid + j * 256) * 16, src + tid + j * 256);
        CP_COMMIT();
    }

    for (int i = tid * 4; i < SMF_WS; i += 1024)
        *(uint4*)(Hs_u + i) = make_uint4(0, 0, 0, 0);
    for (int i = tid; i < G_; i += 256) { bih_s[i] = bih_g[i]; bhh_s[i] = bhh_g[i]; }
    __syncthreads();

    int sc = 0;   // continuous slab counter

    for (int t = 0; t < KS_; t++) {
        for (int c = 0; c < 8; c++) {
            float acc[3][2][2][4];
#pragma unroll
            for (int g = 0; g < 3; g++)
#pragma unroll
                for (int mt = 0; mt < 2; mt++)
#pragma unroll
                    for (int nt = 0; nt < 2; nt++)
#pragma unroll
                        for (int e = 0; e < 4; e++) acc[g][mt][nt][e] = 0.f;

            for (int kq = 0; kq < 4; kq++) {
                const int buf = sc % 3;
                CP_WAIT2();
                __syncthreads();
                const uint32_t* W = Ws_u + buf * SLAB_W;

#pragma unroll
                for (int k8 = 0; k8 < 8; k8++) {
                    uint32_t a[2][4];
                    const int ko = kq * 64 + k8 * 8 + qcol * 2;
#pragma unroll
                    for (int mt = 0; mt < 2; mt++) {
                        const int r = mbase + mt * 16 + qrow;
                        uint2 lo = *(const uint2*)(Hs_u + r * HS_S + ko);
                        uint2 hi = *(const uint2*)(Hs_u + (r + 8) * HS_S + ko);
                        a[mt][0] = lo.x; a[mt][2] = lo.y;
                        a[mt][1] = hi.x; a[mt][3] = hi.y;
                    }
                    const uint32_t* wk = W + (ncol * 8 + k8) * 384 + lane * 2;
#pragma unroll
                    for (int g = 0; g < 3; g++)
#pragma unroll
                        for (int nt = 0; nt < 2; nt++) {
                            uint2 b = *(const uint2*)(wk + g * 128 + nt * 64);
                            mma8(acc[g][0][nt], a[0], b.x, b.y);
                            mma8(acc[g][1][nt], a[1], b.x, b.y);
                        }
                }
                __syncthreads();   // all warps done reading buf before refill
                {
                    const int ns = (sc + 3) & 31;
                    const uint4* src = ((const uint4*)g_wt2) + (size_t)ns * (SLAB_W / 4);
                    uint32_t dst = ws_b + buf * SLAB_W * 4;
#pragma unroll
                    for (int j = 0; j < 6; j++)
                        cp16(dst + (tid + j * 256) * 16, src + tid + j * 256);
                    CP_COMMIT();
                }
                sc++;
            }

            // ---- fused GRU epilogue for chunk c (16 dims per warp-col) ----
#pragma unroll
            for (int nt = 0; nt < 2; nt++) {
                const int dwg = ncol * 128 + c * 16 + nt * 8 + 2 * qcol;
                const float2 bhr = *(const float2*)(bhh_s + dwg);
                const float2 bhz = *(const float2*)(bhh_s + 256 + dwg);
                const float2 bhn = *(const float2*)(bhh_s + 512 + dwg);
#pragma unroll
                for (int mt = 0; mt < 2; mt++)
#pragma unroll
                    for (int eh = 0; eh < 2; eh++) {
                        const int row   = mbase + mt * 16 + eh * 8 + qrow;
                        const int chain = n0 + row;
                        const int lp    = (chain & (L_ - 1)) - (KS_ - 1) + t;
                        float2 gr, gz, gn;
                        if (lp >= 0) {
                            const float* gp = g_gi + (size_t)(chain - (KS_ - 1) + t) * G_;
                            gr = *(const float2*)(gp + dwg);
                            gz = *(const float2*)(gp + 256 + dwg);
                            gn = *(const float2*)(gp + 512 + dwg);
                        } else {
                            gr = *(const float2*)(bih_s + dwg);
                            gz = *(const float2*)(bih_s + 256 + dwg);
                            gn = *(const float2*)(bih_s + 512 + dwg);
                        }
                        float2 hv;
#pragma unroll
                        for (int e2 = 0; e2 < 2; e2++) {
                            const float ghr = acc[0][mt][nt][eh * 2 + e2] + (e2 ? bhr.y : bhr.x);
                            const float ghz = acc[1][mt][nt][eh * 2 + e2] + (e2 ? bhz.y : bhz.x);
                            const float ghn = acc[2][mt][nt][eh * 2 + e2] + (e2 ? bhn.y : bhn.x);
                            const float rg = fsig((e2 ? gr.y : gr.x) + ghr);
                            const float zg = fsig((e2 ? gz.y : gz.x) + ghz);
                            const float ng = ftanhf((e2 ? gn.y : gn.x) + rg * ghn);
                            const float ho = Hs_f[row * HS_S + permk(dwg + e2)];
                            (e2 ? hv.y : hv.x) = (1.f - zg) * ng + zg * ho;
                        }
                        if (t == KS_ - 1)
                            *(float2*)(out + (size_t)chain * D_ + dwg) = hv;
                        else
                            *(float2*)(g_hnew + ((size_t)blockIdx.x * 128 + row) * D_ + dwg) = hv;
                    }
            }
        }

        if (t < KS_ - 1) {
            __syncthreads();   // epilogue gmem writes by this block visible to it
            const float* src = g_hnew + (size_t)blockIdx.x * 128 * D_;
            for (int i = tid; i < 128 * D_; i += 256)
                Hs_u[(i >> 8) * HS_S + permk(i & 255)] = tf32_of(src[i]);
            __syncthreads();
        }
    }
    CP_WAIT0();
    __syncthreads();
}

// ---------------------------------------------------------------------------
// Launch
// ---------------------------------------------------------------------------
extern "C" void kernel_launch(void* const* d_in, const int* in_sizes, int n_in,
                              void* d_out, int out_size)
{
    const float* x   = (const float*)d_in[0];
    const float* Wih = (const float*)d_in[1];
    const float* Whh = (const float*)d_in[2];
    const float* bih = (const float*)d_in[3];
    const float* bhh = (const float*)d_in[4];
    float* out = (float*)d_out;

    wprep_kernel<<<768, 256>>>(Whh);

    cudaFuncSetAttribute(gi_mma_kernel,
                         cudaFuncAttributeMaxDynamicSharedMemorySize, GI_SMEM_BYTES);
    dim3 gi_grid(NCH_ / 128, G_ / 128);
    gi_mma_kernel<<<gi_grid, 256, GI_SMEM_BYTES>>>(x, Wih, bih);

    cudaFuncSetAttribute(rnn_mma_kernel,
                         cudaFuncAttributeMaxDynamicSharedMemorySize, RNN_SMEM_BYTES);
    rnn_mma_kernel<<<128, 256, RNN_SMEM_BYTES>>>(bih, bhh, out);
}

// round 8
// speedup vs baseline: 1.4380x; 1.4380x over previous
#include <cuda_runtime.h>
#include <stdint.h>
#include <math.h>

// LocalRNN: B=16, L=1024, D=256, ksize=16
#define B_   16
#define L_   1024
#define D_   256
#define KS_  16
#define G_   768
#define NCH_ (B_ * L_)

// Static device scratch
__device__ float    g_gi[(size_t)NCH_ * G_];          // gi[chain][gate_dim]
__device__ uint32_t g_wt2[196608];                    // W_hh tf32, mma-fragment order
__device__ float    g_hnew[(size_t)128 * 128 * D_];   // per-CTA new-h scratch

__device__ __forceinline__ float fsig(float x)   { return __fdividef(1.f, 1.f + __expf(-x)); }
__device__ __forceinline__ float ftanhf(float x) { return __fdividef(2.f, 1.f + __expf(-2.f * x)) - 1.f; }
__device__ __forceinline__ uint32_t tf32_of(float f) {
    uint32_t v; asm("cvt.rna.tf32.f32 %0, %1;" : "=r"(v) : "f"(f)); return v;
}
// paired-k permutation: (k, k+4) adjacent within each 8-group
__device__ __forceinline__ int permk(int k) {
    return (k & ~7) + ((k & 3) << 1) + ((k >> 2) & 1);
}
__device__ __forceinline__ void mma8(float* d, const uint32_t* a, uint32_t b0, uint32_t b1) {
    asm volatile(
        "mma.sync.aligned.m16n8k8.row.col.f32.tf32.tf32.f32 "
        "{%0,%1,%2,%3}, {%4,%5,%6,%7}, {%8,%9}, {%0,%1,%2,%3};"
        : "+f"(d[0]), "+f"(d[1]), "+f"(d[2]), "+f"(d[3])
        : "r"(a[0]), "r"(a[1]), "r"(a[2]), "r"(a[3]), "r"(b0), "r"(b1));
}

// ---------------------------------------------------------------------------
// Prep: W_hh -> tf32 in mma-fragment order for 4x32-dim chunking.
// slab = c*4 + kq (12288 words). Word within slab:
//   ((((ncol*8+k8)*3+g)*4+nt)*32+lane)*2 + r
// maps to W_hh[g*256 + ncol*128 + c*32 + nt*8 + (lane>>2)]
//             [kq*64 + k8*8 + (lane&3) + r*4]
// ---------------------------------------------------------------------------
__global__ void wprep_kernel(const float* __restrict__ Whh) {
    int e = blockIdx.x * 256 + threadIdx.x;
    if (e >= 196608) return;
    int slab = e / 12288, w = e % 12288;
    int c = slab >> 2, kq = slab & 3;
    int r = w & 1, lane = (w >> 1) & 31;
    int u = w >> 6;          // 0..191
    int nt = u & 3;
    int v = u >> 2;          // 0..47
    int g = v % 3, m = v / 3;
    int k8 = m & 7, ncol = m >> 3;
    int qcol = lane & 3, qrow = lane >> 2;
    int k   = kq * 64 + k8 * 8 + qcol + r * 4;
    int dim = ncol * 128 + c * 32 + nt * 8 + qrow;
    g_wt2[e] = tf32_of(Whh[(size_t)(g * 256 + dim) * D_ + k]);
}

// ---------------------------------------------------------------------------
// gi = x @ W_ih^T + b_ih  (fp32 SIMT, known good; gi[chain][gate_dim])
// ---------------------------------------------------------------------------
__global__ __launch_bounds__(256) void gi_gemm_kernel(
    const float* __restrict__ x,
    const float* __restrict__ Wih,
    const float* __restrict__ bih)
{
    __shared__ float As[16][68];
    __shared__ float Bs[16][68];

    const int mt  = blockIdx.x * 64;
    const int nt  = blockIdx.y * 64;
    const int tid = threadIdx.x;
    const int txx = tid & 15;
    const int tyy = tid >> 4;

    float acc[4][4];
#pragma unroll
    for (int i = 0; i < 4; i++)
#pragma unroll
        for (int j = 0; j < 4; j++) acc[i][j] = 0.f;

    for (int kt = 0; kt < D_; kt += 16) {
#pragma unroll
        for (int i = 0; i < 4; i++) {
            int idx = i * 256 + tid;
            int m = idx >> 4, k = idx & 15;
            As[k][m] = x[(size_t)(mt + m) * D_ + kt + k];
            Bs[k][m] = Wih[(size_t)(nt + m) * D_ + kt + k];
        }
        __syncthreads();
#pragma unroll
        for (int k = 0; k < 16; k++) {
            float a[4], b[4];
#pragma unroll
            for (int i = 0; i < 4; i++) a[i] = As[k][tyy * 4 + i];
#pragma unroll
            for (int i = 0; i < 4; i++) b[i] = Bs[k][txx * 4 + i];
#pragma unroll
            for (int i = 0; i < 4; i++)
#pragma unroll
                for (int j = 0; j < 4; j++)
                    acc[i][j] = fmaf(a[i], b[j], acc[i][j]);
        }
        __syncthreads();
    }

#pragma unroll
    for (int i = 0; i < 4; i++) {
        int n = mt + tyy * 4 + i;
#pragma unroll
        for (int j = 0; j < 4; j++) {
            int g = nt + txx * 4 + j;
            g_gi[(size_t)n * G_ + g] = acc[i][j] + bih[g];
        }
    }
}

// ---------------------------------------------------------------------------
// Main recurrence (R6 structure). 128 CTAs x 128 chains, 8 warps (4M x 2Ncol).
// Smem words: Hs[128][264] @0 (33792) | Ws slab 12288 @33792
//             bih @46080 | bhh @46848  -> 47616 words = 190464 B
// Per step: 4 chunks (32 dims per warp-col) x 4 kq slabs; each slab staged by
// a linear 12xLDG.128 copy from fragment-ordered g_wt2; fused GRU epilogue.
// ---------------------------------------------------------------------------
#define HS_S   264
#define SLAB_W 12288
#define SMF_WS  (128 * HS_S)            // 33792
#define SMF_BIH (SMF_WS + SLAB_W)       // 46080
#define SMF_BHH (SMF_BIH + G_)
#define RNN_SMEM_BYTES ((SMF_BHH + G_) * 4)

__global__ __launch_bounds__(256, 1) void rnn_mma_kernel(
    const float* __restrict__ bih_g,
    const float* __restrict__ bhh_g,
    float* __restrict__ out)
{
    extern __shared__ uint32_t sm[];
    uint32_t* Hs_u  = sm;
    float*    Hs_f  = (float*)sm;
    uint32_t* Ws_u  = sm + SMF_WS;
    float*    bih_s = (float*)(sm + SMF_BIH);
    float*    bhh_s = (float*)(sm + SMF_BHH);

    const int tid = threadIdx.x;
    const int lane = tid & 31, wid = tid >> 5;
    const int qrow = lane >> 2, qcol = lane & 3;
    const int mbase = (wid & 3) * 32;
    const int ncol  = wid >> 2;
    const int n0 = blockIdx.x * 128;

    for (int i = tid * 4; i < SMF_WS; i += 1024)
        *(uint4*)(Hs_u + i) = make_uint4(0, 0, 0, 0);
    for (int i = tid; i < G_; i += 256) { bih_s[i] = bih_g[i]; bhh_s[i] = bhh_g[i]; }
    __syncthreads();

    for (int t = 0; t < KS_; t++) {
        for (int c = 0; c < 4; c++) {
            float acc[3][2][4][4];
#pragma unroll
            for (int g = 0; g < 3; g++)
#pragma unroll
                for (int mt = 0; mt < 2; mt++)
#pragma unroll
                    for (int nt = 0; nt < 4; nt++)
#pragma unroll
                        for (int e = 0; e < 4; e++) acc[g][mt][nt][e] = 0.f;

            for (int kq = 0; kq < 4; kq++) {
                __syncthreads();   // previous slab fully consumed
                {   // stage slab (c,kq): pure linear coalesced copy
                    const uint4* src = ((const uint4*)g_wt2)
                                     + (size_t)(c * 4 + kq) * (SLAB_W / 4);
                    uint4* dst = (uint4*)Ws_u;
#pragma unroll
                    for (int j = 0; j < 12; j++)
                        dst[tid + j * 256] = src[tid + j * 256];
                }
                __syncthreads();

#pragma unroll
                for (int k8 = 0; k8 < 8; k8++) {
                    uint32_t a[2][4];
                    const int ko = kq * 64 + k8 * 8 + qcol * 2;
#pragma unroll
                    for (int mt = 0; mt < 2; mt++) {
                        const int r = mbase + mt * 16 + qrow;
                        uint2 lo = *(const uint2*)(Hs_u + r * HS_S + ko);
                        uint2 hi = *(const uint2*)(Hs_u + (r + 8) * HS_S + ko);
                        a[mt][0] = lo.x; a[mt][2] = lo.y;
                        a[mt][1] = hi.x; a[mt][3] = hi.y;
                    }
                    const uint32_t* wk = Ws_u + (ncol * 8 + k8) * 768 + lane * 2;
#pragma unroll
                    for (int g = 0; g < 3; g++)
#pragma unroll
                        for (int nt = 0; nt < 4; nt++) {
                            uint2 b = *(const uint2*)(wk + g * 256 + nt * 64);
                            mma8(acc[g][0][nt], a[0], b.x, b.y);
                            mma8(acc[g][1][nt], a[1], b.x, b.y);
                        }
                }
            }

            // ---- fused GRU epilogue for chunk c (32 dims per warp-col) ----
#pragma unroll
            for (int nt = 0; nt < 4; nt++) {
                const int dwg = ncol * 128 + c * 32 + nt * 8 + 2 * qcol;
                const float2 bhr = *(const float2*)(bhh_s + dwg);
                const float2 bhz = *(const float2*)(bhh_s + 256 + dwg);
                const float2 bhn = *(const float2*)(bhh_s + 512 + dwg);
#pragma unroll
                for (int mt = 0; mt < 2; mt++)
#pragma unroll
                    for (int eh = 0; eh < 2; eh++) {
                        const int row   = mbase + mt * 16 + eh * 8 + qrow;
                        const int chain = n0 + row;
                        const int lp    = (chain & (L_ - 1)) - (KS_ - 1) + t;
                        float2 gr, gz, gn;
                        if (lp >= 0) {
                            const float* gp = g_gi + (size_t)(chain - (KS_ - 1) + t) * G_;
                            gr = *(const float2*)(gp + dwg);
                            gz = *(const float2*)(gp + 256 + dwg);
                            gn = *(const float2*)(gp + 512 + dwg);
                        } else {
                            gr = *(const float2*)(bih_s + dwg);
                            gz = *(const float2*)(bih_s + 256 + dwg);
                            gn = *(const float2*)(bih_s + 512 + dwg);
                        }
                        float2 hv;
#pragma unroll
                        for (int e2 = 0; e2 < 2; e2++) {
                            const float ghr = acc[0][mt][nt][eh * 2 + e2] + (e2 ? bhr.y : bhr.x);
                            const float ghz = acc[1][mt][nt][eh * 2 + e2] + (e2 ? bhz.y : bhz.x);
                            const float ghn = acc[2][mt][nt][eh * 2 + e2] + (e2 ? bhn.y : bhn.x);
                            const float rg = fsig((e2 ? gr.y : gr.x) + ghr);
                            const float zg = fsig((e2 ? gz.y : gz.x) + ghz);
                            const float ng = ftanhf((e2 ? gn.y : gn.x) + rg * ghn);
                            const float ho = Hs_f[row * HS_S + permk(dwg + e2)];
                            (e2 ? hv.y : hv.x) = (1.f - zg) * ng + zg * ho;
                        }
                        if (t == KS_ - 1)
                            *(float2*)(out + (size_t)chain * D_ + dwg) = hv;
                        else
                            *(float2*)(g_hnew + ((size_t)blockIdx.x * 128 + row) * D_ + dwg) = hv;
                    }
            }
        }

        if (t < KS_ - 1) {
            __syncthreads();   // epilogue gmem writes by this block visible to it
            const float* src = g_hnew + (size_t)blockIdx.x * 128 * D_;
            for (int i = tid; i < 128 * D_; i += 256)
                Hs_u[(i >> 8) * HS_S + permk(i & 255)] = tf32_of(src[i]);
            __syncthreads();
        }
    }
}

// ---------------------------------------------------------------------------
// Launch
// ---------------------------------------------------------------------------
extern "C" void kernel_launch(void* const* d_in, const int* in_sizes, int n_in,
                              void* d_out, int out_size)
{
    const float* x   = (const float*)d_in[0];
    const float* Wih = (const float*)d_in[1];
    const float* Whh = (const float*)d_in[2];
    const float* bih = (const float*)d_in[3];
    const float* bhh = (const float*)d_in[4];
    float* out = (float*)d_out;

    wprep_kernel<<<768, 256>>>(Whh);

    dim3 gi_grid(NCH_ / 64, G_ / 64);
    gi_gemm_kernel<<<gi_grid, 256>>>(x, Wih, bih);

    cudaFuncSetAttribute(rnn_mma_kernel,
                         cudaFuncAttributeMaxDynamicSharedMemorySize, RNN_SMEM_BYTES);
    rnn_mma_kernel<<<128, 256, RNN_SMEM_BYTES>>>(bih, bhh, out);
}

// round 9
// speedup vs baseline: 1.6897x; 1.1750x over previous
#include <cuda_runtime.h>
#include <stdint.h>
#include <math.h>

// LocalRNN: B=16, L=1024, D=256, ksize=16
#define B_   16
#define L_   1024
#define D_   256
#define KS_  16
#define G_   768
#define NCH_ (B_ * L_)

// Static device scratch
__device__ float    g_gi[(size_t)NCH_ * G_];          // gi[chain][gate_dim]
__device__ uint32_t g_wt2[196608];                    // W_hh tf32, mma-fragment order
__device__ float    g_hnew[(size_t)128 * 128 * D_];   // per-CTA new-h scratch

__device__ __forceinline__ float fsig(float x)   { return __fdividef(1.f, 1.f + __expf(-x)); }
__device__ __forceinline__ float ftanhf(float x) { return __fdividef(2.f, 1.f + __expf(-2.f * x)) - 1.f; }
__device__ __forceinline__ uint32_t tf32_of(float f) {
    uint32_t v; asm("cvt.rna.tf32.f32 %0, %1;" : "=r"(v) : "f"(f)); return v;
}
// paired-k permutation: (k, k+4) adjacent within each 8-group
__device__ __forceinline__ int permk(int k) {
    return (k & ~7) + ((k & 3) << 1) + ((k >> 2) & 1);
}
__device__ __forceinline__ void mma8(float* d, const uint32_t* a, uint32_t b0, uint32_t b1) {
    asm volatile(
        "mma.sync.aligned.m16n8k8.row.col.f32.tf32.tf32.f32 "
        "{%0,%1,%2,%3}, {%4,%5,%6,%7}, {%8,%9}, {%0,%1,%2,%3};"
        : "+f"(d[0]), "+f"(d[1]), "+f"(d[2]), "+f"(d[3])
        : "r"(a[0]), "r"(a[1]), "r"(a[2]), "r"(a[3]), "r"(b0), "r"(b1));
}

// ---------------------------------------------------------------------------
// Prep: W_hh -> tf32, mma-fragment order, B-pairs vectorized for LDS.128.
// slab = c*4 + kq (12288 words). Within slab, 16 blocks of 768 words
// (block = ncol*8 + k8): word = g*256 + nt2*128 + lane*4 + o, where
// nt = nt2*2 + (o>>1), r = o&1. Maps to
//   W_hh[g*256 + ncol*128 + c*32 + nt*8 + (lane>>2)][kq*64 + k8*8 + (lane&3) + r*4]
// ---------------------------------------------------------------------------
__global__ void wprep_kernel(const float* __restrict__ Whh) {
    int e = blockIdx.x * 256 + threadIdx.x;
    if (e >= 196608) return;
    int slab = e / 12288, w = e % 12288;
    int c = slab >> 2, kq = slab & 3;
    int block = w / 768, rem = w % 768;
    int g = rem >> 8;
    int r2 = rem & 255;
    int nt2 = r2 >> 7;
    int rr = r2 & 127;
    int lane = rr >> 2, o = rr & 3;
    int nt = nt2 * 2 + (o >> 1), r = o & 1;
    int k8 = block & 7, ncol = block >> 3;
    int k   = kq * 64 + k8 * 8 + (lane & 3) + r * 4;
    int dim = ncol * 128 + c * 32 + nt * 8 + (lane >> 2);
    g_wt2[e] = tf32_of(Whh[(size_t)(g * 256 + dim) * D_ + k]);
}

// ---------------------------------------------------------------------------
// gi = x @ W_ih^T + b_ih via tf32 mma (proven in R7). grid (128, 6), 256 thr.
// ---------------------------------------------------------------------------
#define GX_S 72
#define GW_S 136
#define GI_SMEM_BYTES ((128 * GX_S + 64 * GW_S) * 4)

__global__ __launch_bounds__(256) void gi_mma_kernel(
    const float* __restrict__ x,
    const float* __restrict__ Wih,
    const float* __restrict__ bih)
{
    extern __shared__ uint32_t gsm[];
    uint32_t* Xs  = gsm;
    uint32_t* Wst = gsm + 128 * GX_S;

    const int tid = threadIdx.x;
    const int lane = tid & 31, wid = tid >> 5;
    const int qrow = lane >> 2, qcol = lane & 3;
    const int mbase = (wid & 3) * 32;
    const int ncol  = wid >> 2;
    const int mt0 = blockIdx.x * 128;
    const int ntile = blockIdx.y * 128;

    float acc[2][8][4];
#pragma unroll
    for (int mt = 0; mt < 2; mt++)
#pragma unroll
        for (int nt = 0; nt < 8; nt++)
#pragma unroll
            for (int e = 0; e < 4; e++) acc[mt][nt][e] = 0.f;

    for (int kq = 0; kq < 4; kq++) {
        __syncthreads();
        {   // stage x tile (paired-k layout)
            const int row = tid >> 1, half = tid & 1;
            const float* xp = x + (size_t)(mt0 + row) * D_ + kq * 64 + half * 32;
#pragma unroll
            for (int i = 0; i < 4; i++) {
                float4 v0 = *(const float4*)(xp + i * 8);
                float4 v1 = *(const float4*)(xp + i * 8 + 4);
                uint32_t* d = Xs + row * GX_S + half * 32 + i * 8;
                d[0] = tf32_of(v0.x); d[1] = tf32_of(v1.x);
                d[2] = tf32_of(v0.y); d[3] = tf32_of(v1.y);
                d[4] = tf32_of(v0.z); d[5] = tf32_of(v1.z);
                d[6] = tf32_of(v0.w); d[7] = tf32_of(v1.w);
            }
        }
        {   // stage Wih tile transposed: Wst[k][gd]
            const int gd = tid >> 1, half = tid & 1;
            const float* wp = Wih + (size_t)(ntile + gd) * D_ + kq * 64 + half * 32;
#pragma unroll
            for (int i = 0; i < 8; i++) {
                float4 v = *(const float4*)(wp + i * 4);
                int kk = half * 32 + i * 4;
                Wst[(kk + 0) * GW_S + gd] = tf32_of(v.x);
                Wst[(kk + 1) * GW_S + gd] = tf32_of(v.y);
                Wst[(kk + 2) * GW_S + gd] = tf32_of(v.z);
                Wst[(kk + 3) * GW_S + gd] = tf32_of(v.w);
            }
        }
        __syncthreads();

#pragma unroll
        for (int k8 = 0; k8 < 8; k8++) {
            uint32_t a[2][4];
#pragma unroll
            for (int mt = 0; mt < 2; mt++) {
                const int r = mbase + mt * 16 + qrow;
                uint2 lo = *(const uint2*)(Xs + r * GX_S + k8 * 8 + qcol * 2);
                uint2 hi = *(const uint2*)(Xs + (r + 8) * GX_S + k8 * 8 + qcol * 2);
                a[mt][0] = lo.x; a[mt][2] = lo.y;
                a[mt][1] = hi.x; a[mt][3] = hi.y;
            }
            const uint32_t* wb = Wst + (k8 * 8 + qcol) * GW_S + ncol * 64 + qrow;
#pragma unroll
            for (int nt = 0; nt < 8; nt++) {
                uint32_t b0 = wb[nt * 8];
                uint32_t b1 = wb[4 * GW_S + nt * 8];
                mma8(acc[0][nt], a[0], b0, b1);
                mma8(acc[1][nt], a[1], b0, b1);
            }
        }
    }

#pragma unroll
    for (int nt = 0; nt < 8; nt++) {
        const int gd = ntile + ncol * 64 + nt * 8 + 2 * qcol;
        const float2 bv = *(const float2*)(bih + gd);
#pragma unroll
        for (int mt = 0; mt < 2; mt++)
#pragma unroll
            for (int eh = 0; eh < 2; eh++) {
                const int chain = mt0 + mbase + mt * 16 + eh * 8 + qrow;
                float2 o;
                o.x = acc[mt][nt][eh * 2 + 0] + bv.x;
                o.y = acc[mt][nt][eh * 2 + 1] + bv.y;
                *(float2*)(g_gi + (size_t)chain * G_ + gd) = o;
            }
    }
}

// ---------------------------------------------------------------------------
// Main recurrence. 128 CTAs x 128 chains, 8 warps (4M x 2Ncol).
// Register-prefetched W staging: each thread LDGs the NEXT 48KB slab into 12
// uint4 regs while MMAing the current one; staging window = 12 STS.128 only.
// ---------------------------------------------------------------------------
#define HS_S   264
#define SLAB_W 12288
#define SMF_WS  (128 * HS_S)            // 33792
#define SMF_BIH (SMF_WS + SLAB_W)       // 46080
#define SMF_BHH (SMF_BIH + G_)
#define RNN_SMEM_BYTES ((SMF_BHH + G_) * 4)

__global__ __launch_bounds__(256, 1) void rnn_mma_kernel(
    const float* __restrict__ bih_g,
    const float* __restrict__ bhh_g,
    float* __restrict__ out)
{
    extern __shared__ uint32_t sm[];
    uint32_t* Hs_u  = sm;
    float*    Hs_f  = (float*)sm;
    uint32_t* Ws_u  = sm + SMF_WS;
    float*    bih_s = (float*)(sm + SMF_BIH);
    float*    bhh_s = (float*)(sm + SMF_BHH);

    const int tid = threadIdx.x;
    const int lane = tid & 31, wid = tid >> 5;
    const int qrow = lane >> 2, qcol = lane & 3;
    const int mbase = (wid & 3) * 32;
    const int ncol  = wid >> 2;
    const int n0 = blockIdx.x * 128;

    for (int i = tid * 4; i < SMF_WS; i += 1024)
        *(uint4*)(Hs_u + i) = make_uint4(0, 0, 0, 0);
    for (int i = tid; i < G_; i += 256) { bih_s[i] = bih_g[i]; bhh_s[i] = bhh_g[i]; }

    // prefetch slab 0 into registers
    uint4 pf[12];
    {
        const uint4* src = (const uint4*)g_wt2;
#pragma unroll
        for (int j = 0; j < 12; j++) pf[j] = src[tid + j * 256];
    }
    __syncthreads();

    int sc = 0;   // global slab counter (slab = sc & 15)

    for (int t = 0; t < KS_; t++) {
        for (int c = 0; c < 4; c++) {
            float acc[3][2][4][4];
#pragma unroll
            for (int g = 0; g < 3; g++)
#pragma unroll
                for (int mt = 0; mt < 2; mt++)
#pragma unroll
                    for (int nt = 0; nt < 4; nt++)
#pragma unroll
                        for (int e = 0; e < 4; e++) acc[g][mt][nt][e] = 0.f;

            for (int kq = 0; kq < 4; kq++) {
                __syncthreads();   // previous slab fully consumed by all warps
                {   // commit prefetched slab to smem (pure STS.128)
                    uint4* dst = (uint4*)Ws_u;
#pragma unroll
                    for (int j = 0; j < 12; j++) dst[tid + j * 256] = pf[j];
                }
                __syncthreads();   // slab ready
                {   // issue LDG for the next slab; hides under the MMA phase
                    const uint4* src = ((const uint4*)g_wt2)
                                     + (size_t)((sc + 1) & 15) * (SLAB_W / 4);
#pragma unroll
                    for (int j = 0; j < 12; j++) pf[j] = src[tid + j * 256];
                }

#pragma unroll
                for (int k8 = 0; k8 < 8; k8++) {
                    uint32_t a[2][4];
                    const int ko = kq * 64 + k8 * 8 + qcol * 2;
#pragma unroll
                    for (int mt = 0; mt < 2; mt++) {
                        const int r = mbase + mt * 16 + qrow;
                        uint2 lo = *(const uint2*)(Hs_u + r * HS_S + ko);
                        uint2 hi = *(const uint2*)(Hs_u + (r + 8) * HS_S + ko);
                        a[mt][0] = lo.x; a[mt][2] = lo.y;
                        a[mt][1] = hi.x; a[mt][3] = hi.y;
                    }
                    const uint32_t* wk = Ws_u + (ncol * 8 + k8) * 768 + lane * 4;
#pragma unroll
                    for (int g = 0; g < 3; g++)
#pragma unroll
                        for (int nt2 = 0; nt2 < 2; nt2++) {
                            uint4 bv = *(const uint4*)(wk + g * 256 + nt2 * 128);
                            mma8(acc[g][0][nt2 * 2 + 0], a[0], bv.x, bv.y);
                            mma8(acc[g][1][nt2 * 2 + 0], a[1], bv.x, bv.y);
                            mma8(acc[g][0][nt2 * 2 + 1], a[0], bv.z, bv.w);
                            mma8(acc[g][1][nt2 * 2 + 1], a[1], bv.z, bv.w);
                        }
                }
                sc++;
            }

            // ---- fused GRU epilogue for chunk c (32 dims per warp-col) ----
#pragma unroll
            for (int nt = 0; nt < 4; nt++) {
                const int dwg = ncol * 128 + c * 32 + nt * 8 + 2 * qcol;
                const float2 bhr = *(const float2*)(bhh_s + dwg);
                const float2 bhz = *(const float2*)(bhh_s + 256 + dwg);
                const float2 bhn = *(const float2*)(bhh_s + 512 + dwg);
#pragma unroll
                for (int mt = 0; mt < 2; mt++)
#pragma unroll
                    for (int eh = 0; eh < 2; eh++) {
                        const int row   = mbase + mt * 16 + eh * 8 + qrow;
                        const int chain = n0 + row;
                        const int lp    = (chain & (L_ - 1)) - (KS_ - 1) + t;
                        float2 gr, gz, gn;
                        if (lp >= 0) {
                            const float* gp = g_gi + (size_t)(chain - (KS_ - 1) + t) * G_;
                            gr = *(const float2*)(gp + dwg);
                            gz = *(const float2*)(gp + 256 + dwg);
                            gn = *(const float2*)(gp + 512 + dwg);
                        } else {
                            gr = *(const float2*)(bih_s + dwg);
                            gz = *(const float2*)(bih_s + 256 + dwg);
                            gn = *(const float2*)(bih_s + 512 + dwg);
                        }
                        float2 hv;
#pragma unroll
                        for (int e2 = 0; e2 < 2; e2++) {
                            const float ghr = acc[0][mt][nt][eh * 2 + e2] + (e2 ? bhr.y : bhr.x);
                            const float ghz = acc[1][mt][nt][eh * 2 + e2] + (e2 ? bhz.y : bhz.x);
                            const float ghn = acc[2][mt][nt][eh * 2 + e2] + (e2 ? bhn.y : bhn.x);
                            const float rg = fsig((e2 ? gr.y : gr.x) + ghr);
                            const float zg = fsig((e2 ? gz.y : gz.x) + ghz);
                            const float ng = ftanhf((e2 ? gn.y : gn.x) + rg * ghn);
                            const float ho = Hs_f[row * HS_S + permk(dwg + e2)];
                            (e2 ? hv.y : hv.x) = (1.f - zg) * ng + zg * ho;
                        }
                        if (t == KS_ - 1)
                            *(float2*)(out + (size_t)chain * D_ + dwg) = hv;
                        else
                            *(float2*)(g_hnew + ((size_t)blockIdx.x * 128 + row) * D_ + dwg) = hv;
                    }
            }
        }

        if (t < KS_ - 1) {
            __syncthreads();   // epilogue gmem writes by this block visible to it
            const float* src = g_hnew + (size_t)blockIdx.x * 128 * D_;
            for (int i = tid; i < 128 * D_; i += 256)
                Hs_u[(i >> 8) * HS_S + permk(i & 255)] = tf32_of(src[i]);
            __syncthreads();
        }
    }
}

// ---------------------------------------------------------------------------
// Launch
// ---------------------------------------------------------------------------
extern "C" void kernel_launch(void* const* d_in, const int* in_sizes, int n_in,
                              void* d_out, int out_size)
{
    const float* x   = (const float*)d_in[0];
    const float* Wih = (const float*)d_in[1];
    const float* Whh = (const float*)d_in[2];
    const float* bih = (const float*)d_in[3];
    const float* bhh = (const float*)d_in[4];
    float* out = (float*)d_out;

    wprep_kernel<<<768, 256>>>(Whh);

    cudaFuncSetAttribute(gi_mma_kernel,
                         cudaFuncAttributeMaxDynamicSharedMemorySize, GI_SMEM_BYTES);
    dim3 gi_grid(NCH_ / 128, G_ / 128);
    gi_mma_kernel<<<gi_grid, 256, GI_SMEM_BYTES>>>(x, Wih, bih);

    cudaFuncSetAttribute(rnn_mma_kernel,
                         cudaFuncAttributeMaxDynamicSharedMemorySize, RNN_SMEM_BYTES);
    rnn_mma_kernel<<<128, 256, RNN_SMEM_BYTES>>>(bih, bhh, out);
}

// round 10
// speedup vs baseline: 1.7144x; 1.0146x over previous
#include <cuda_runtime.h>
#include <stdint.h>
#include <math.h>

// LocalRNN: B=16, L=1024, D=256, ksize=16
#define B_   16
#define L_   1024
#define D_   256
#define KS_  16
#define G_   768
#define NCH_ (B_ * L_)

// Static device scratch
__device__ float    g_gi[(size_t)NCH_ * G_];          // gi[chain][gate_dim]
__device__ uint32_t g_wt2[196608];                    // W_hh tf32, half-slab fragment order
__device__ float    g_hnew[(size_t)128 * 128 * D_];   // per-CTA new-h scratch

__device__ __forceinline__ float fsig(float x)   { return __fdividef(1.f, 1.f + __expf(-x)); }
__device__ __forceinline__ float ftanhf(float x) { return __fdividef(2.f, 1.f + __expf(-2.f * x)) - 1.f; }
__device__ __forceinline__ uint32_t tf32_of(float f) {
    uint32_t v; asm("cvt.rna.tf32.f32 %0, %1;" : "=r"(v) : "f"(f)); return v;
}
// paired-k permutation: (k, k+4) adjacent within each 8-group
__device__ __forceinline__ int permk(int k) {
    return (k & ~7) + ((k & 3) << 1) + ((k >> 2) & 1);
}
__device__ __forceinline__ void mma8(float* d, const uint32_t* a, uint32_t b0, uint32_t b1) {
    asm volatile(
        "mma.sync.aligned.m16n8k8.row.col.f32.tf32.tf32.f32 "
        "{%0,%1,%2,%3}, {%4,%5,%6,%7}, {%8,%9}, {%0,%1,%2,%3};"
        : "+f"(d[0]), "+f"(d[1]), "+f"(d[2]), "+f"(d[3])
        : "r"(a[0]), "r"(a[1]), "r"(a[2]), "r"(a[3]), "r"(b0), "r"(b1));
}

// ---------------------------------------------------------------------------
// Prep: W_hh -> tf32, HALF-SLAB fragment order (B-pairs vectorized, LDS.128).
// half-slab hs = ((c*4+kq)*2+kh), 6144 words. Within: block = ncol*4+k8m (768 w):
//   word = g*256 + nt2*128 + lane*4 + o;  nt = nt2*2+(o>>1), r = o&1, k8 = kh*4+k8m
// maps to W_hh[g*256 + ncol*128 + c*32 + nt*8 + (lane>>2)]
//             [kq*64 + k8*8 + (lane&3) + r*4]
// ---------------------------------------------------------------------------
__global__ void wprep_kernel(const float* __restrict__ Whh) {
    int e = blockIdx.x * 256 + threadIdx.x;
    if (e >= 196608) return;
    int hs = e / 6144, w6 = e % 6144;
    int kh = hs & 1, ckq = hs >> 1;
    int c = ckq >> 2, kq = ckq & 3;
    int block = w6 / 768, rem = w6 % 768;
    int g = rem >> 8;
    int r2 = rem & 255;
    int nt2 = r2 >> 7;
    int rr = r2 & 127;
    int lane = rr >> 2, o = rr & 3;
    int nt = nt2 * 2 + (o >> 1), r = o & 1;
    int k8m = block & 3, ncol = block >> 2;
    int k8 = kh * 4 + k8m;
    int k   = kq * 64 + k8 * 8 + (lane & 3) + r * 4;
    int dim = ncol * 128 + c * 32 + nt * 8 + (lane >> 2);
    g_wt2[e] = tf32_of(Whh[(size_t)(g * 256 + dim) * D_ + k]);
}

// ---------------------------------------------------------------------------
// gi = x @ W_ih^T + b_ih via tf32 mma. grid (128, 6), 256 thr.
// ---------------------------------------------------------------------------
#define GX_S 72
#define GW_S 136
#define GI_SMEM_BYTES ((128 * GX_S + 64 * GW_S) * 4)

__global__ __launch_bounds__(256) void gi_mma_kernel(
    const float* __restrict__ x,
    const float* __restrict__ Wih,
    const float* __restrict__ bih)
{
    extern __shared__ uint32_t gsm[];
    uint32_t* Xs  = gsm;
    uint32_t* Wst = gsm + 128 * GX_S;

    const int tid = threadIdx.x;
    const int lane = tid & 31, wid = tid >> 5;
    const int qrow = lane >> 2, qcol = lane & 3;
    const int mbase = (wid & 3) * 32;
    const int ncol  = wid >> 2;
    const int mt0 = blockIdx.x * 128;
    const int ntile = blockIdx.y * 128;

    float acc[2][8][4];
#pragma unroll
    for (int mt = 0; mt < 2; mt++)
#pragma unroll
        for (int nt = 0; nt < 8; nt++)
#pragma unroll
            for (int e = 0; e < 4; e++) acc[mt][nt][e] = 0.f;

    for (int kq = 0; kq < 4; kq++) {
        __syncthreads();
        {   // stage x tile (paired-k layout)
            const int row = tid >> 1, half = tid & 1;
            const float* xp = x + (size_t)(mt0 + row) * D_ + kq * 64 + half * 32;
#pragma unroll
            for (int i = 0; i < 4; i++) {
                float4 v0 = *(const float4*)(xp + i * 8);
                float4 v1 = *(const float4*)(xp + i * 8 + 4);
                uint32_t* d = Xs + row * GX_S + half * 32 + i * 8;
                d[0] = tf32_of(v0.x); d[1] = tf32_of(v1.x);
                d[2] = tf32_of(v0.y); d[3] = tf32_of(v1.y);
                d[4] = tf32_of(v0.z); d[5] = tf32_of(v1.z);
                d[6] = tf32_of(v0.w); d[7] = tf32_of(v1.w);
            }
        }
        {   // stage Wih tile transposed: Wst[k][gd]
            const int gd = tid >> 1, half = tid & 1;
            const float* wp = Wih + (size_t)(ntile + gd) * D_ + kq * 64 + half * 32;
#pragma unroll
            for (int i = 0; i < 8; i++) {
                float4 v = *(const float4*)(wp + i * 4);
                int kk = half * 32 + i * 4;
                Wst[(kk + 0) * GW_S + gd] = tf32_of(v.x);
                Wst[(kk + 1) * GW_S + gd] = tf32_of(v.y);
                Wst[(kk + 2) * GW_S + gd] = tf32_of(v.z);
                Wst[(kk + 3) * GW_S + gd] = tf32_of(v.w);
            }
        }
        __syncthreads();

#pragma unroll
        for (int k8 = 0; k8 < 8; k8++) {
            uint32_t a[2][4];
#pragma unroll
            for (int mt = 0; mt < 2; mt++) {
                const int r = mbase + mt * 16 + qrow;
                uint2 lo = *(const uint2*)(Xs + r * GX_S + k8 * 8 + qcol * 2);
                uint2 hi = *(const uint2*)(Xs + (r + 8) * GX_S + k8 * 8 + qcol * 2);
                a[mt][0] = lo.x; a[mt][2] = lo.y;
                a[mt][1] = hi.x; a[mt][3] = hi.y;
            }
            const uint32_t* wb = Wst + (k8 * 8 + qcol) * GW_S + ncol * 64 + qrow;
#pragma unroll
            for (int nt = 0; nt < 8; nt++) {
                uint32_t b0 = wb[nt * 8];
                uint32_t b1 = wb[4 * GW_S + nt * 8];
                mma8(acc[0][nt], a[0], b0, b1);
                mma8(acc[1][nt], a[1], b0, b1);
            }
        }
    }

#pragma unroll
    for (int nt = 0; nt < 8; nt++) {
        const int gd = ntile + ncol * 64 + nt * 8 + 2 * qcol;
        const float2 bv = *(const float2*)(bih + gd);
#pragma unroll
        for (int mt = 0; mt < 2; mt++)
#pragma unroll
            for (int eh = 0; eh < 2; eh++) {
                const int chain = mt0 + mbase + mt * 16 + eh * 8 + qrow;
                float2 o;
                o.x = acc[mt][nt][eh * 2 + 0] + bv.x;
                o.y = acc[mt][nt][eh * 2 + 1] + bv.y;
                *(float2*)(g_gi + (size_t)chain * G_ + gd) = o;
            }
    }
}

// ---------------------------------------------------------------------------
// Main recurrence. 128 CTAs x 128 chains, 8 warps (4M x 2Ncol).
// Half-slab (6144 w) double-buffered W pipeline: STS(next) + LDG(next+1)
// overlap the current MMA phase; ONE barrier per phase.
// ---------------------------------------------------------------------------
#define HS_S   264
#define HSLAB  6144
#define SMF_WS  (128 * HS_S)            // 33792
#define SMF_BIH (SMF_WS + 2 * HSLAB)    // 46080
#define SMF_BHH (SMF_BIH + G_)
#define RNN_SMEM_BYTES ((SMF_BHH + G_) * 4)

__global__ __launch_bounds__(256, 1) void rnn_mma_kernel(
    const float* __restrict__ bih_g,
    const float* __restrict__ bhh_g,
    float* __restrict__ out)
{
    extern __shared__ uint32_t sm[];
    uint32_t* Hs_u  = sm;
    float*    Hs_f  = (float*)sm;
    uint32_t* Ws_u  = sm + SMF_WS;
    float*    bih_s = (float*)(sm + SMF_BIH);
    float*    bhh_s = (float*)(sm + SMF_BHH);

    const int tid = threadIdx.x;
    const int lane = tid & 31, wid = tid >> 5;
    const int qrow = lane >> 2, qcol = lane & 3;
    const int mbase = (wid & 3) * 32;
    const int ncol  = wid >> 2;
    const int n0 = blockIdx.x * 128;

    for (int i = tid * 4; i < SMF_WS; i += 1024)
        *(uint4*)(Hs_u + i) = make_uint4(0, 0, 0, 0);
    for (int i = tid; i < G_; i += 256) { bih_s[i] = bih_g[i]; bhh_s[i] = bhh_g[i]; }

    uint4 pf[6];
    {   // hs0 -> buf0, prefetch hs1
        const uint4* s = (const uint4*)g_wt2;
#pragma unroll
        for (int j = 0; j < 6; j++) pf[j] = s[tid + j * 256];
        uint4* d = (uint4*)Ws_u;
#pragma unroll
        for (int j = 0; j < 6; j++) d[tid + j * 256] = pf[j];
#pragma unroll
        for (int j = 0; j < 6; j++) pf[j] = s[1536 + tid + j * 256];
    }
    __syncthreads();

    int sc = 0;   // half-slab phase counter (hs = sc & 31)

    for (int t = 0; t < KS_; t++) {
        for (int c = 0; c < 4; c++) {
            float acc[3][2][4][4];
#pragma unroll
            for (int g = 0; g < 3; g++)
#pragma unroll
                for (int mt = 0; mt < 2; mt++)
#pragma unroll
                    for (int nt = 0; nt < 4; nt++)
#pragma unroll
                        for (int e = 0; e < 4; e++) acc[g][mt][nt][e] = 0.f;

            for (int ph = 0; ph < 8; ph++) {   // kq = ph>>1, kh = ph&1
                const uint32_t* W = Ws_u + (sc & 1) * HSLAB;
                {   // commit next half-slab (regs -> other buffer), overlaps MMA
                    uint4* d = (uint4*)(Ws_u + ((sc + 1) & 1) * HSLAB);
#pragma unroll
                    for (int j = 0; j < 6; j++) d[tid + j * 256] = pf[j];
                }
                {   // prefetch half-slab sc+2
                    const uint4* s = ((const uint4*)g_wt2)
                                   + (size_t)((sc + 2) & 31) * (HSLAB / 4);
#pragma unroll
                    for (int j = 0; j < 6; j++) pf[j] = s[tid + j * 256];
                }

                const int kq = ph >> 1, kh = ph & 1;
#pragma unroll
                for (int k8m = 0; k8m < 4; k8m++) {
                    const int k8 = kh * 4 + k8m;
                    uint32_t a[2][4];
                    const int ko = kq * 64 + k8 * 8 + qcol * 2;
#pragma unroll
                    for (int mt = 0; mt < 2; mt++) {
                        const int r = mbase + mt * 16 + qrow;
                        uint2 lo = *(const uint2*)(Hs_u + r * HS_S + ko);
                        uint2 hi = *(const uint2*)(Hs_u + (r + 8) * HS_S + ko);
                        a[mt][0] = lo.x; a[mt][2] = lo.y;
                        a[mt][1] = hi.x; a[mt][3] = hi.y;
                    }
                    const uint32_t* wk = W + (ncol * 4 + k8m) * 768 + lane * 4;
#pragma unroll
                    for (int g = 0; g < 3; g++)
#pragma unroll
                        for (int nt2 = 0; nt2 < 2; nt2++) {
                            uint4 bv = *(const uint4*)(wk + g * 256 + nt2 * 128);
                            mma8(acc[g][0][nt2 * 2 + 0], a[0], bv.x, bv.y);
                            mma8(acc[g][1][nt2 * 2 + 0], a[1], bv.x, bv.y);
                            mma8(acc[g][0][nt2 * 2 + 1], a[0], bv.z, bv.w);
                            mma8(acc[g][1][nt2 * 2 + 1], a[1], bv.z, bv.w);
                        }
                }
                __syncthreads();
                sc++;
            }

            // ---- fused GRU epilogue for chunk c (32 dims per warp-col) ----
#pragma unroll
            for (int nt = 0; nt < 4; nt++) {
                const int dwg = ncol * 128 + c * 32 + nt * 8 + 2 * qcol;
                const float2 bhr = *(const float2*)(bhh_s + dwg);
                const float2 bhz = *(const float2*)(bhh_s + 256 + dwg);
                const float2 bhn = *(const float2*)(bhh_s + 512 + dwg);
#pragma unroll
                for (int mt = 0; mt < 2; mt++)
#pragma unroll
                    for (int eh = 0; eh < 2; eh++) {
                        const int row   = mbase + mt * 16 + eh * 8 + qrow;
                        const int chain = n0 + row;
                        const int lp    = (chain & (L_ - 1)) - (KS_ - 1) + t;
                        float2 gr, gz, gn;
                        if (lp >= 0) {
                            const float* gp = g_gi + (size_t)(chain - (KS_ - 1) + t) * G_;
                            gr = *(const float2*)(gp + dwg);
                            gz = *(const float2*)(gp + 256 + dwg);
                            gn = *(const float2*)(gp + 512 + dwg);
                        } else {
                            gr = *(const float2*)(bih_s + dwg);
                            gz = *(const float2*)(bih_s + 256 + dwg);
                            gn = *(const float2*)(bih_s + 512 + dwg);
                        }
                        float2 hv;
#pragma unroll
                        for (int e2 = 0; e2 < 2; e2++) {
                            const float ghr = acc[0][mt][nt][eh * 2 + e2] + (e2 ? bhr.y : bhr.x);
                            const float ghz = acc[1][mt][nt][eh * 2 + e2] + (e2 ? bhz.y : bhz.x);
                            const float ghn = acc[2][mt][nt][eh * 2 + e2] + (e2 ? bhn.y : bhn.x);
                            const float rg = fsig((e2 ? gr.y : gr.x) + ghr);
                            const float zg = fsig((e2 ? gz.y : gz.x) + ghz);
                            const float ng = ftanhf((e2 ? gn.y : gn.x) + rg * ghn);
                            const float ho = Hs_f[row * HS_S + permk(dwg + e2)];
                            (e2 ? hv.y : hv.x) = (1.f - zg) * ng + zg * ho;
                        }
                        if (t == KS_ - 1)
                            *(float2*)(out + (size_t)chain * D_ + dwg) = hv;
                        else
                            *(float2*)(g_hnew + ((size_t)blockIdx.x * 128 + row) * D_ + dwg) = hv;
                    }
            }
        }

        if (t < KS_ - 1) {
            __syncthreads();   // epilogue gmem writes by this block visible to it
            const uint4* src = (const uint4*)(g_hnew + (size_t)blockIdx.x * 128 * D_);
#pragma unroll
            for (int it = 0; it < 32; it++) {
                const int i = tid + it * 256;      // uint4 index, 8192 total
                uint4 v = src[i];
                const int row = i >> 6;            // 64 uint4 per 256-dim row
                const int d0 = (i & 63) * 4;
                uint32_t* hrow = Hs_u + row * HS_S;
                hrow[permk(d0 + 0)] = tf32_of(__uint_as_float(v.x));
                hrow[permk(d0 + 1)] = tf32_of(__uint_as_float(v.y));
                hrow[permk(d0 + 2)] = tf32_of(__uint_as_float(v.z));
                hrow[permk(d0 + 3)] = tf32_of(__uint_as_float(v.w));
            }
            __syncthreads();
        }
    }
}

// ---------------------------------------------------------------------------
// Launch — gi first (ncu capture lands on launch index ≡ 0 mod 3)
// ---------------------------------------------------------------------------
extern "C" void kernel_launch(void* const* d_in, const int* in_sizes, int n_in,
                              void* d_out, int out_size)
{
    const float* x   = (const float*)d_in[0];
    const float* Wih = (const float*)d_in[1];
    const float* Whh = (const float*)d_in[2];
    const float* bih = (const float*)d_in[3];
    const float* bhh = (const float*)d_in[4];
    float* out = (float*)d_out;

    cudaFuncSetAttribute(gi_mma_kernel,
                         cudaFuncAttributeMaxDynamicSharedMemorySize, GI_SMEM_BYTES);
    dim3 gi_grid(NCH_ / 128, G_ / 128);
    gi_mma_kernel<<<gi_grid, 256, GI_SMEM_BYTES>>>(x, Wih, bih);

    wprep_kernel<<<768, 256>>>(Whh);

    cudaFuncSetAttribute(rnn_mma_kernel,
                         cudaFuncAttributeMaxDynamicSharedMemorySize, RNN_SMEM_BYTES);
    rnn_mma_kernel<<<128, 256, RNN_SMEM_BYTES>>>(bih, bhh, out);
}

// round 11
// speedup vs baseline: 2.4566x; 1.4329x over previous
#include <cuda_runtime.h>
#include <cuda_fp16.h>
#include <stdint.h>
#include <math.h>

// LocalRNN: B=16, L=1024, D=256, ksize=16
#define B_   16
#define L_   1024
#define D_   256
#define KS_  16
#define G_   768
#define NCH_ (B_ * L_)

// Static device scratch
__device__ float    g_gi[(size_t)NCH_ * G_];          // gi[chain][gate_dim]
__device__ uint32_t g_wh[98304];                      // W_hh fp16 half2, fragment order (384KB)
__device__ float    g_hnew[(size_t)128 * 128 * D_];   // per-CTA new-h scratch

__device__ __forceinline__ float fsig(float x)   { return __fdividef(1.f, 1.f + __expf(-x)); }
__device__ __forceinline__ float ftanhf(float x) { return __fdividef(2.f, 1.f + __expf(-2.f * x)) - 1.f; }
__device__ __forceinline__ uint32_t tf32_of(float f) {
    uint32_t v; asm("cvt.rna.tf32.f32 %0, %1;" : "=r"(v) : "f"(f)); return v;
}
// paired-word permutation: pairs (w, w+4) adjacent within each 8-group
__device__ __forceinline__ int permw(int w) {
    return (w & ~7) | ((w & 3) << 1) | ((w >> 2) & 1);
}
// half2-word index (paired) for hidden dim d (d even, covers d and d+1)
__device__ __forceinline__ int hword(int d) { return permw(d >> 1); }

__device__ __forceinline__ void mma8(float* d, const uint32_t* a, uint32_t b0, uint32_t b1) {
    asm volatile(
        "mma.sync.aligned.m16n8k8.row.col.f32.tf32.tf32.f32 "
        "{%0,%1,%2,%3}, {%4,%5,%6,%7}, {%8,%9}, {%0,%1,%2,%3};"
        : "+f"(d[0]), "+f"(d[1]), "+f"(d[2]), "+f"(d[3])
        : "r"(a[0]), "r"(a[1]), "r"(a[2]), "r"(a[3]), "r"(b0), "r"(b1));
}
__device__ __forceinline__ void mma16f(float* d, const uint32_t* a, uint32_t b0, uint32_t b1) {
    asm volatile(
        "mma.sync.aligned.m16n8k16.row.col.f32.f16.f16.f32 "
        "{%0,%1,%2,%3}, {%4,%5,%6,%7}, {%8,%9}, {%0,%1,%2,%3};"
        : "+f"(d[0]), "+f"(d[1]), "+f"(d[2]), "+f"(d[3])
        : "r"(a[0]), "r"(a[1]), "r"(a[2]), "r"(a[3]), "r"(b0), "r"(b1));
}

// ---------------------------------------------------------------------------
// Prep: W_hh -> fp16 half2, m16n8k16 fragment order.
// slab = c*4+kq (6144 words, 24KB). block = ncol*4+k16m (768 words):
//   word = g*256 + nt2*128 + lane*4 + o;  nt = nt2*2+(o>>1), r = o&1
// half2 = (W[n][k], W[n][k+1]) with n = g*256+ncol*128+c*32+nt*8+(lane>>2),
//   k = kq*64 + k16m*16 + 2*(lane&3) + r*8
// ---------------------------------------------------------------------------
__global__ void wprep_kernel(const float* __restrict__ Whh) {
    int e = blockIdx.x * 256 + threadIdx.x;
    if (e >= 98304) return;
    int slab = e / 6144, w6 = e % 6144;
    int c = slab >> 2, kq = slab & 3;
    int block = w6 / 768, rem = w6 % 768;
    int g = rem >> 8;
    int r2 = rem & 255;
    int nt2 = r2 >> 7;
    int rr = r2 & 127;
    int lane = rr >> 2, o = rr & 3;
    int nt = nt2 * 2 + (o >> 1), r = o & 1;
    int k16m = block & 3, ncol = block >> 2;
    int k   = kq * 64 + k16m * 16 + 2 * (lane & 3) + r * 8;
    int dim = ncol * 128 + c * 32 + nt * 8 + (lane >> 2);
    const float* wr = Whh + (size_t)(g * 256 + dim) * D_ + k;
    __half2 h2 = __floats2half2_rn(wr[0], wr[1]);
    g_wh[e] = *(uint32_t*)&h2;
}

// ---------------------------------------------------------------------------
// gi = x @ W_ih^T + b_ih via tf32 mma (unchanged, known good). grid (128,6).
// ---------------------------------------------------------------------------
#define GX_S 72
#define GW_S 136
#define GI_SMEM_BYTES ((128 * GX_S + 64 * GW_S) * 4)

__global__ __launch_bounds__(256) void gi_mma_kernel(
    const float* __restrict__ x,
    const float* __restrict__ Wih,
    const float* __restrict__ bih)
{
    extern __shared__ uint32_t gsm[];
    uint32_t* Xs  = gsm;
    uint32_t* Wst = gsm + 128 * GX_S;

    const int tid = threadIdx.x;
    const int lane = tid & 31, wid = tid >> 5;
    const int qrow = lane >> 2, qcol = lane & 3;
    const int mbase = (wid & 3) * 32;
    const int ncol  = wid >> 2;
    const int mt0 = blockIdx.x * 128;
    const int ntile = blockIdx.y * 128;

    float acc[2][8][4];
#pragma unroll
    for (int mt = 0; mt < 2; mt++)
#pragma unroll
        for (int nt = 0; nt < 8; nt++)
#pragma unroll
            for (int e = 0; e < 4; e++) acc[mt][nt][e] = 0.f;

    for (int kq = 0; kq < 4; kq++) {
        __syncthreads();
        {
            const int row = tid >> 1, half = tid & 1;
            const float* xp = x + (size_t)(mt0 + row) * D_ + kq * 64 + half * 32;
#pragma unroll
            for (int i = 0; i < 4; i++) {
                float4 v0 = *(const float4*)(xp + i * 8);
                float4 v1 = *(const float4*)(xp + i * 8 + 4);
                uint32_t* d = Xs + row * GX_S + half * 32 + i * 8;
                d[0] = tf32_of(v0.x); d[1] = tf32_of(v1.x);
                d[2] = tf32_of(v0.y); d[3] = tf32_of(v1.y);
                d[4] = tf32_of(v0.z); d[5] = tf32_of(v1.z);
                d[6] = tf32_of(v0.w); d[7] = tf32_of(v1.w);
            }
        }
        {
            const int gd = tid >> 1, half = tid & 1;
            const float* wp = Wih + (size_t)(ntile + gd) * D_ + kq * 64 + half * 32;
#pragma unroll
            for (int i = 0; i < 8; i++) {
                float4 v = *(const float4*)(wp + i * 4);
                int kk = half * 32 + i * 4;
                Wst[(kk + 0) * GW_S + gd] = tf32_of(v.x);
                Wst[(kk + 1) * GW_S + gd] = tf32_of(v.y);
                Wst[(kk + 2) * GW_S + gd] = tf32_of(v.z);
                Wst[(kk + 3) * GW_S + gd] = tf32_of(v.w);
            }
        }
        __syncthreads();

#pragma unroll
        for (int k8 = 0; k8 < 8; k8++) {
            uint32_t a[2][4];
#pragma unroll
            for (int mt = 0; mt < 2; mt++) {
                const int r = mbase + mt * 16 + qrow;
                uint2 lo = *(const uint2*)(Xs + r * GX_S + k8 * 8 + qcol * 2);
                uint2 hi = *(const uint2*)(Xs + (r + 8) * GX_S + k8 * 8 + qcol * 2);
                a[mt][0] = lo.x; a[mt][2] = lo.y;
                a[mt][1] = hi.x; a[mt][3] = hi.y;
            }
            const uint32_t* wb = Wst + (k8 * 8 + qcol) * GW_S + ncol * 64 + qrow;
#pragma unroll
            for (int nt = 0; nt < 8; nt++) {
                uint32_t b0 = wb[nt * 8];
                uint32_t b1 = wb[4 * GW_S + nt * 8];
                mma8(acc[0][nt], a[0], b0, b1);
                mma8(acc[1][nt], a[1], b0, b1);
            }
        }
    }

#pragma unroll
    for (int nt = 0; nt < 8; nt++) {
        const int gd = ntile + ncol * 64 + nt * 8 + 2 * qcol;
        const float2 bv = *(const float2*)(bih + gd);
#pragma unroll
        for (int mt = 0; mt < 2; mt++)
#pragma unroll
            for (int eh = 0; eh < 2; eh++) {
                const int chain = mt0 + mbase + mt * 16 + eh * 8 + qrow;
                float2 o;
                o.x = acc[mt][nt][eh * 2 + 0] + bv.x;
                o.y = acc[mt][nt][eh * 2 + 1] + bv.y;
                *(float2*)(g_gi + (size_t)chain * G_ + gd) = o;
            }
    }
}

// ---------------------------------------------------------------------------
// Main recurrence, fp16 m16n8k16. 128 CTAs x 128 chains, 8 warps (4M x 2Ncol).
// H in smem as half2 (paired-k words, stride 136 ≡ 8 mod 32: conflict-free
// LDS.64 A-frags). W: 24KB slabs, double-buffered register-prefetch pipeline,
// 16 barriers/step.
// ---------------------------------------------------------------------------
#define HW_S   136                      // half2 words per H row
#define WSLAB  6144
#define SMF_WS  (128 * HW_S)            // 17408 words
#define SMF_BIH (SMF_WS + 2 * WSLAB)    // 29696
#define SMF_BHH (SMF_BIH + G_)
#define RNN_SMEM_BYTES ((SMF_BHH + G_) * 4)   // 124928 B

__global__ __launch_bounds__(256, 1) void rnn_mma_kernel(
    const float* __restrict__ bih_g,
    const float* __restrict__ bhh_g,
    float* __restrict__ out)
{
    extern __shared__ uint32_t sm[];
    uint32_t* Hs_u  = sm;
    uint32_t* Ws_u  = sm + SMF_WS;
    float*    bih_s = (float*)(sm + SMF_BIH);
    float*    bhh_s = (float*)(sm + SMF_BHH);

    const int tid = threadIdx.x;
    const int lane = tid & 31, wid = tid >> 5;
    const int qrow = lane >> 2, qcol = lane & 3;
    const int mbase = (wid & 3) * 32;
    const int ncol  = wid >> 2;
    const int n0 = blockIdx.x * 128;

    for (int i = tid * 4; i < SMF_WS; i += 1024)
        *(uint4*)(Hs_u + i) = make_uint4(0, 0, 0, 0);
    for (int i = tid; i < G_; i += 256) { bih_s[i] = bih_g[i]; bhh_s[i] = bhh_g[i]; }

    uint4 pf[6];
    {   // slab0 -> buf0, prefetch slab1
        const uint4* s = (const uint4*)g_wh;
#pragma unroll
        for (int j = 0; j < 6; j++) pf[j] = s[tid + j * 256];
        uint4* d = (uint4*)Ws_u;
#pragma unroll
        for (int j = 0; j < 6; j++) d[tid + j * 256] = pf[j];
#pragma unroll
        for (int j = 0; j < 6; j++) pf[j] = s[1536 + tid + j * 256];
    }
    __syncthreads();

    int sc = 0;   // slab phase counter (slab = sc & 15)

    for (int t = 0; t < KS_; t++) {
        for (int c = 0; c < 4; c++) {
            float acc[3][2][4][4];
#pragma unroll
            for (int g = 0; g < 3; g++)
#pragma unroll
                for (int mt = 0; mt < 2; mt++)
#pragma unroll
                    for (int nt = 0; nt < 4; nt++)
#pragma unroll
                        for (int e = 0; e < 4; e++) acc[g][mt][nt][e] = 0.f;

            for (int kq = 0; kq < 4; kq++) {
                const uint32_t* W = Ws_u + (sc & 1) * WSLAB;
                {   // commit next slab (regs -> other buffer), overlaps MMA
                    uint4* d = (uint4*)(Ws_u + ((sc + 1) & 1) * WSLAB);
#pragma unroll
                    for (int j = 0; j < 6; j++) d[tid + j * 256] = pf[j];
                }
                {   // prefetch slab sc+2
                    const uint4* s = ((const uint4*)g_wh)
                                   + (size_t)((sc + 2) & 15) * (WSLAB / 4);
#pragma unroll
                    for (int j = 0; j < 6; j++) pf[j] = s[tid + j * 256];
                }

#pragma unroll
                for (int k16m = 0; k16m < 4; k16m++) {
                    const int k16 = kq * 4 + k16m;
                    const int ko  = k16 * 8 + 2 * qcol;   // half2-word index
                    uint32_t a[2][4];
#pragma unroll
                    for (int mt = 0; mt < 2; mt++) {
                        const int r = mbase + mt * 16 + qrow;
                        uint2 lo = *(const uint2*)(Hs_u + r * HW_S + ko);
                        uint2 hi = *(const uint2*)(Hs_u + (r + 8) * HW_S + ko);
                        a[mt][0] = lo.x; a[mt][1] = hi.x;
                        a[mt][2] = lo.y; a[mt][3] = hi.y;
                    }
                    const uint32_t* wk = W + (ncol * 4 + k16m) * 768 + lane * 4;
#pragma unroll
                    for (int g = 0; g < 3; g++)
#pragma unroll
                        for (int nt2 = 0; nt2 < 2; nt2++) {
                            uint4 bv = *(const uint4*)(wk + g * 256 + nt2 * 128);
                            mma16f(acc[g][0][nt2 * 2 + 0], a[0], bv.x, bv.y);
                            mma16f(acc[g][1][nt2 * 2 + 0], a[1], bv.x, bv.y);
                            mma16f(acc[g][0][nt2 * 2 + 1], a[0], bv.z, bv.w);
                            mma16f(acc[g][1][nt2 * 2 + 1], a[1], bv.z, bv.w);
                        }
                }
                __syncthreads();
                sc++;
            }

            // ---- fused GRU epilogue for chunk c (32 dims per warp-col) ----
#pragma unroll
            for (int nt = 0; nt < 4; nt++) {
                const int dwg = ncol * 128 + c * 32 + nt * 8 + 2 * qcol;
                const float2 bhr = *(const float2*)(bhh_s + dwg);
                const float2 bhz = *(const float2*)(bhh_s + 256 + dwg);
                const float2 bhn = *(const float2*)(bhh_s + 512 + dwg);
                const int hw = hword(dwg);
#pragma unroll
                for (int mt = 0; mt < 2; mt++)
#pragma unroll
                    for (int eh = 0; eh < 2; eh++) {
                        const int row   = mbase + mt * 16 + eh * 8 + qrow;
                        const int chain = n0 + row;
                        const int lp    = (chain & (L_ - 1)) - (KS_ - 1) + t;
                        float2 gr, gz, gn;
                        if (lp >= 0) {
                            const float* gp = g_gi + (size_t)(chain - (KS_ - 1) + t) * G_;
                            gr = *(const float2*)(gp + dwg);
                            gz = *(const float2*)(gp + 256 + dwg);
                            gn = *(const float2*)(gp + 512 + dwg);
                        } else {
                            gr = *(const float2*)(bih_s + dwg);
                            gz = *(const float2*)(bih_s + 256 + dwg);
                            gn = *(const float2*)(bih_s + 512 + dwg);
                        }
                        const __half2 hh = *(const __half2*)(Hs_u + row * HW_S + hw);
                        const float2 hof = __half22float2(hh);
                        float2 hv;
#pragma unroll
                        for (int e2 = 0; e2 < 2; e2++) {
                            const float ghr = acc[0][mt][nt][eh * 2 + e2] + (e2 ? bhr.y : bhr.x);
                            const float ghz = acc[1][mt][nt][eh * 2 + e2] + (e2 ? bhz.y : bhz.x);
                            const float ghn = acc[2][mt][nt][eh * 2 + e2] + (e2 ? bhn.y : bhn.x);
                            const float rg = fsig((e2 ? gr.y : gr.x) + ghr);
                            const float zg = fsig((e2 ? gz.y : gz.x) + ghz);
                            const float ng = ftanhf((e2 ? gn.y : gn.x) + rg * ghn);
                            const float ho = e2 ? hof.y : hof.x;
                            (e2 ? hv.y : hv.x) = (1.f - zg) * ng + zg * ho;
                        }
                        if (t == KS_ - 1)
                            *(float2*)(out + (size_t)chain * D_ + dwg) = hv;
                        else
                            *(float2*)(g_hnew + ((size_t)blockIdx.x * 128 + row) * D_ + dwg) = hv;
                    }
            }
        }

        if (t < KS_ - 1) {
            __syncthreads();   // epilogue gmem writes by this block visible to it
            const uint4* src = (const uint4*)(g_hnew + (size_t)blockIdx.x * 128 * D_);
#pragma unroll
            for (int it = 0; it < 32; it++) {
                const int i = tid + it * 256;      // uint4 index, 8192 total
                uint4 v = src[i];
                const int row = i >> 6;
                const int w0 = (i & 63) * 2;       // half2-word index (pre-perm)
                __half2 p0 = __floats2half2_rn(__uint_as_float(v.x), __uint_as_float(v.y));
                __half2 p1 = __floats2half2_rn(__uint_as_float(v.z), __uint_as_float(v.w));
                uint32_t* hrow = Hs_u + row * HW_S;
                hrow[permw(w0)]     = *(uint32_t*)&p0;
                hrow[permw(w0 + 1)] = *(uint32_t*)&p1;
            }
            __syncthreads();
        }
    }
}

// ---------------------------------------------------------------------------
// Launch — gi first (ncu capture lands on launch index ≡ 0 mod 3)
// ---------------------------------------------------------------------------
extern "C" void kernel_launch(void* const* d_in, const int* in_sizes, int n_in,
                              void* d_out, int out_size)
{
    const float* x   = (const float*)d_in[0];
    const float* Wih = (const float*)d_in[1];
    const float* Whh = (const float*)d_in[2];
    const float* bih = (const float*)d_in[3];
    const float* bhh = (const float*)d_in[4];
    float* out = (float*)d_out;

    cudaFuncSetAttribute(gi_mma_kernel,
                         cudaFuncAttributeMaxDynamicSharedMemorySize, GI_SMEM_BYTES);
    dim3 gi_grid(NCH_ / 128, G_ / 128);
    gi_mma_kernel<<<gi_grid, 256, GI_SMEM_BYTES>>>(x, Wih, bih);

    wprep_kernel<<<384, 256>>>(Whh);

    cudaFuncSetAttribute(rnn_mma_kernel,
                         cudaFuncAttributeMaxDynamicSharedMemorySize, RNN_SMEM_BYTES);
    rnn_mma_kernel<<<128, 256, RNN_SMEM_BYTES>>>(bih, bhh, out);
}

// round 12
// speedup vs baseline: 2.6053x; 1.0605x over previous
#include <cuda_runtime.h>
#include <cuda_fp16.h>
#include <stdint.h>
#include <math.h>

// LocalRNN: B=16, L=1024, D=256, ksize=16
#define B_   16
#define L_   1024
#define D_   256
#define KS_  16
#define G_   768
#define NCH_ (B_ * L_)

// Static device scratch
__device__ float    g_gi[(size_t)NCH_ * G_];   // gi[chain][gate_dim]
__device__ uint32_t g_wh[98304];               // W_hh fp16 half2, fragment order (384KB)

__device__ __forceinline__ float fsig(float x)   { return __fdividef(1.f, 1.f + __expf(-x)); }
__device__ __forceinline__ float ftanhf(float x) { return __fdividef(2.f, 1.f + __expf(-2.f * x)) - 1.f; }
// paired-word permutation: pairs (w, w+4) adjacent within each 8-group
__device__ __forceinline__ int permw(int w) {
    return (w & ~7) | ((w & 3) << 1) | ((w >> 2) & 1);
}
// half2-word index (paired) for hidden dim d (d even, covers d and d+1)
__device__ __forceinline__ int hword(int d) { return permw(d >> 1); }

__device__ __forceinline__ void mma16f(float* d, const uint32_t* a, uint32_t b0, uint32_t b1) {
    asm volatile(
        "mma.sync.aligned.m16n8k16.row.col.f32.f16.f16.f32 "
        "{%0,%1,%2,%3}, {%4,%5,%6,%7}, {%8,%9}, {%0,%1,%2,%3};"
        : "+f"(d[0]), "+f"(d[1]), "+f"(d[2]), "+f"(d[3])
        : "r"(a[0]), "r"(a[1]), "r"(a[2]), "r"(a[3]), "r"(b0), "r"(b1));
}

// ---------------------------------------------------------------------------
// Prep: W_hh -> fp16 half2, m16n8k16 fragment order (slab = c*4+kq, 6144 w).
// ---------------------------------------------------------------------------
__global__ void wprep_kernel(const float* __restrict__ Whh) {
    int e = blockIdx.x * 256 + threadIdx.x;
    if (e >= 98304) return;
    int slab = e / 6144, w6 = e % 6144;
    int c = slab >> 2, kq = slab & 3;
    int block = w6 / 768, rem = w6 % 768;
    int g = rem >> 8;
    int r2 = rem & 255;
    int nt2 = r2 >> 7;
    int rr = r2 & 127;
    int lane = rr >> 2, o = rr & 3;
    int nt = nt2 * 2 + (o >> 1), r = o & 1;
    int k16m = block & 3, ncol = block >> 2;
    int k   = kq * 64 + k16m * 16 + 2 * (lane & 3) + r * 8;
    int dim = ncol * 128 + c * 32 + nt * 8 + (lane >> 2);
    const float* wr = Whh + (size_t)(g * 256 + dim) * D_ + k;
    __half2 h2 = __floats2half2_rn(wr[0], wr[1]);
    g_wh[e] = *(uint32_t*)&h2;
}

// ---------------------------------------------------------------------------
// gi = x @ W_ih^T + b_ih via fp16 mma. grid (128, 6), 256 thr.
// X (128x256 fp16, paired-word layout) and Wih tile (128x256 fp16, fragment
// layout) staged ONCE; mainloop of 16 k16 iterations is barrier-free.
// ---------------------------------------------------------------------------
#define GXW_S 136                        // half2 words per X row
#define GI_XS_W (128 * GXW_S)            // 17408
#define GI_WS_W 16384                    // 16 k16 * 16 ntg * 64
#define GI_SMEM_BYTES ((GI_XS_W + GI_WS_W) * 4)   // 135168 B

__global__ __launch_bounds__(256) void gi_mma_kernel(
    const float* __restrict__ x,
    const float* __restrict__ Wih,
    const float* __restrict__ bih)
{
    extern __shared__ uint32_t gsm[];
    uint32_t* Xs  = gsm;
    uint32_t* Wst = gsm + GI_XS_W;

    const int tid = threadIdx.x;
    const int lane = tid & 31, wid = tid >> 5;
    const int qrow = lane >> 2, qcol = lane & 3;
    const int mbase = (wid & 3) * 32;
    const int ncol  = wid >> 2;
    const int mt0 = blockIdx.x * 128;
    const int ntile = blockIdx.y * 128;

    {   // stage X: row = tid>>1, k-half = tid&1 (128 floats -> 64 half2 words)
        const int row = tid >> 1, half = tid & 1;
        const float* xp = x + (size_t)(mt0 + row) * D_ + half * 128;
        uint32_t* xr = Xs + row * GXW_S;
#pragma unroll
        for (int i = 0; i < 16; i++) {
            float4 v0 = *(const float4*)(xp + i * 8);
            float4 v1 = *(const float4*)(xp + i * 8 + 4);
            const int w0 = half * 64 + i * 4;
            __half2 p0 = __floats2half2_rn(v0.x, v0.y);
            __half2 p1 = __floats2half2_rn(v0.z, v0.w);
            __half2 p2 = __floats2half2_rn(v1.x, v1.y);
            __half2 p3 = __floats2half2_rn(v1.z, v1.w);
            xr[permw(w0 + 0)] = *(uint32_t*)&p0;
            xr[permw(w0 + 1)] = *(uint32_t*)&p1;
            xr[permw(w0 + 2)] = *(uint32_t*)&p2;
            xr[permw(w0 + 3)] = *(uint32_t*)&p3;
        }
    }
    {   // stage Wih tile in fragment order: gd = tid>>1, k-half = tid&1
        const int gd = tid >> 1, half = tid & 1;
        const float* wp = Wih + (size_t)(ntile + gd) * D_ + half * 128;
        const int base = (gd >> 3) * 64 + ((gd & 7) << 3);  // + ((k>>1)&3)*2 + r
#pragma unroll
        for (int i = 0; i < 16; i++) {
            float4 v0 = *(const float4*)(wp + i * 8);
            float4 v1 = *(const float4*)(wp + i * 8 + 4);
            const float vv[8] = {v0.x, v0.y, v0.z, v0.w, v1.x, v1.y, v1.z, v1.w};
#pragma unroll
            for (int j = 0; j < 4; j++) {
                const int k = half * 128 + i * 8 + 2 * j;
                __half2 h2 = __floats2half2_rn(vv[2 * j], vv[2 * j + 1]);
                const int word = (k >> 4) * 1024 + base + (((k >> 1) & 3) << 1) + ((k >> 3) & 1);
                Wst[word] = *(uint32_t*)&h2;
            }
        }
    }
    __syncthreads();

    float acc[2][8][4];
#pragma unroll
    for (int mt = 0; mt < 2; mt++)
#pragma unroll
        for (int nt = 0; nt < 8; nt++)
#pragma unroll
            for (int e = 0; e < 4; e++) acc[mt][nt][e] = 0.f;

#pragma unroll
    for (int k16 = 0; k16 < 16; k16++) {
        const int ko = k16 * 8 + 2 * qcol;
        uint32_t a[2][4];
#pragma unroll
        for (int mt = 0; mt < 2; mt++) {
            const int r = mbase + mt * 16 + qrow;
            uint2 lo = *(const uint2*)(Xs + r * GXW_S + ko);
            uint2 hi = *(const uint2*)(Xs + (r + 8) * GXW_S + ko);
            a[mt][0] = lo.x; a[mt][1] = hi.x;
            a[mt][2] = lo.y; a[mt][3] = hi.y;
        }
        const uint32_t* wb = Wst + k16 * 1024 + ncol * 512 + lane * 2;
#pragma unroll
        for (int nt = 0; nt < 8; nt++) {
            uint2 b = *(const uint2*)(wb + nt * 64);
            mma16f(acc[0][nt], a[0], b.x, b.y);
            mma16f(acc[1][nt], a[1], b.x, b.y);
        }
    }

#pragma unroll
    for (int nt = 0; nt < 8; nt++) {
        const int gd = ntile + ncol * 64 + nt * 8 + 2 * qcol;
        const float2 bv = *(const float2*)(bih + gd);
#pragma unroll
        for (int mt = 0; mt < 2; mt++)
#pragma unroll
            for (int eh = 0; eh < 2; eh++) {
                const int chain = mt0 + mbase + mt * 16 + eh * 8 + qrow;
                float2 o;
                o.x = acc[mt][nt][eh * 2 + 0] + bv.x;
                o.y = acc[mt][nt][eh * 2 + 1] + bv.y;
                *(float2*)(g_gi + (size_t)chain * G_ + gd) = o;
            }
    }
}

// ---------------------------------------------------------------------------
// Main recurrence, fp16 m16n8k16, DOUBLE-BUFFERED H in smem (no gmem h
// round-trip). 128 CTAs x 128 chains, 8 warps (4M x 2Ncol).
// Smem words: H0 @0 (17408) | H1 @17408 | Ws 2x6144 @34816 | bih/bhh @47104
// ---------------------------------------------------------------------------
#define HW_S   136
#define HBUF_W (128 * HW_S)             // 17408
#define WSLAB  6144
#define SMF_WS  (2 * HBUF_W)            // 34816
#define SMF_BIH (SMF_WS + 2 * WSLAB)    // 47104
#define SMF_BHH (SMF_BIH + G_)
#define RNN_SMEM_BYTES ((SMF_BHH + G_) * 4)   // 194560 B

__global__ __launch_bounds__(256, 1) void rnn_mma_kernel(
    const float* __restrict__ bih_g,
    const float* __restrict__ bhh_g,
    float* __restrict__ out)
{
    extern __shared__ uint32_t sm[];
    uint32_t* Ws_u  = sm + SMF_WS;
    float*    bih_s = (float*)(sm + SMF_BIH);
    float*    bhh_s = (float*)(sm + SMF_BHH);

    const int tid = threadIdx.x;
    const int lane = tid & 31, wid = tid >> 5;
    const int qrow = lane >> 2, qcol = lane & 3;
    const int mbase = (wid & 3) * 32;
    const int ncol  = wid >> 2;
    const int n0 = blockIdx.x * 128;

    for (int i = tid * 4; i < HBUF_W; i += 1024)
        *(uint4*)(sm + i) = make_uint4(0, 0, 0, 0);
    for (int i = tid; i < G_; i += 256) { bih_s[i] = bih_g[i]; bhh_s[i] = bhh_g[i]; }

    uint4 pf[6];
    {   // slab0 -> buf0, prefetch slab1
        const uint4* s = (const uint4*)g_wh;
#pragma unroll
        for (int j = 0; j < 6; j++) pf[j] = s[tid + j * 256];
        uint4* d = (uint4*)Ws_u;
#pragma unroll
        for (int j = 0; j < 6; j++) d[tid + j * 256] = pf[j];
#pragma unroll
        for (int j = 0; j < 6; j++) pf[j] = s[1536 + tid + j * 256];
    }
    __syncthreads();

    int sc = 0;   // slab phase counter (slab = sc & 15)

    for (int t = 0; t < KS_; t++) {
        uint32_t* Hcur = sm + (t & 1) * HBUF_W;
        uint32_t* Hnxt = sm + ((t + 1) & 1) * HBUF_W;

        for (int c = 0; c < 4; c++) {
            float acc[3][2][4][4];
#pragma unroll
            for (int g = 0; g < 3; g++)
#pragma unroll
                for (int mt = 0; mt < 2; mt++)
#pragma unroll
                    for (int nt = 0; nt < 4; nt++)
#pragma unroll
                        for (int e = 0; e < 4; e++) acc[g][mt][nt][e] = 0.f;

            for (int kq = 0; kq < 4; kq++) {
                const uint32_t* W = Ws_u + (sc & 1) * WSLAB;
                {   // commit next slab (regs -> other buffer), overlaps MMA
                    uint4* d = (uint4*)(Ws_u + ((sc + 1) & 1) * WSLAB);
#pragma unroll
                    for (int j = 0; j < 6; j++) d[tid + j * 256] = pf[j];
                }
                {   // prefetch slab sc+2
                    const uint4* s = ((const uint4*)g_wh)
                                   + (size_t)((sc + 2) & 15) * (WSLAB / 4);
#pragma unroll
                    for (int j = 0; j < 6; j++) pf[j] = s[tid + j * 256];
                }

#pragma unroll
                for (int k16m = 0; k16m < 4; k16m++) {
                    const int k16 = kq * 4 + k16m;
                    const int ko  = k16 * 8 + 2 * qcol;
                    uint32_t a[2][4];
#pragma unroll
                    for (int mt = 0; mt < 2; mt++) {
                        const int r = mbase + mt * 16 + qrow;
                        uint2 lo = *(const uint2*)(Hcur + r * HW_S + ko);
                        uint2 hi = *(const uint2*)(Hcur + (r + 8) * HW_S + ko);
                        a[mt][0] = lo.x; a[mt][1] = hi.x;
                        a[mt][2] = lo.y; a[mt][3] = hi.y;
                    }
                    const uint32_t* wk = W + (ncol * 4 + k16m) * 768 + lane * 4;
#pragma unroll
                    for (int g = 0; g < 3; g++)
#pragma unroll
                        for (int nt2 = 0; nt2 < 2; nt2++) {
                            uint4 bv = *(const uint4*)(wk + g * 256 + nt2 * 128);
                            mma16f(acc[g][0][nt2 * 2 + 0], a[0], bv.x, bv.y);
                            mma16f(acc[g][1][nt2 * 2 + 0], a[1], bv.x, bv.y);
                            mma16f(acc[g][0][nt2 * 2 + 1], a[0], bv.z, bv.w);
                            mma16f(acc[g][1][nt2 * 2 + 1], a[1], bv.z, bv.w);
                        }
                }
                __syncthreads();
                sc++;
            }

            // ---- fused GRU epilogue for chunk c (32 dims per warp-col) ----
#pragma unroll
            for (int nt = 0; nt < 4; nt++) {
                const int dwg = ncol * 128 + c * 32 + nt * 8 + 2 * qcol;
                const float2 bhr = *(const float2*)(bhh_s + dwg);
                const float2 bhz = *(const float2*)(bhh_s + 256 + dwg);
                const float2 bhn = *(const float2*)(bhh_s + 512 + dwg);
                const int hw = hword(dwg);
#pragma unroll
                for (int mt = 0; mt < 2; mt++)
#pragma unroll
                    for (int eh = 0; eh < 2; eh++) {
                        const int row   = mbase + mt * 16 + eh * 8 + qrow;
                        const int chain = n0 + row;
                        const int lp    = (chain & (L_ - 1)) - (KS_ - 1) + t;
                        float2 gr, gz, gn;
                        if (lp >= 0) {
                            const float* gp = g_gi + (size_t)(chain - (KS_ - 1) + t) * G_;
                            gr = *(const float2*)(gp + dwg);
                            gz = *(const float2*)(gp + 256 + dwg);
                            gn = *(const float2*)(gp + 512 + dwg);
                        } else {
                            gr = *(const float2*)(bih_s + dwg);
                            gz = *(const float2*)(bih_s + 256 + dwg);
                            gn = *(const float2*)(bih_s + 512 + dwg);
                        }
                        const __half2 hh = *(const __half2*)(Hcur + row * HW_S + hw);
                        const float2 hof = __half22float2(hh);
                        float2 hv;
#pragma unroll
                        for (int e2 = 0; e2 < 2; e2++) {
                            const float ghr = acc[0][mt][nt][eh * 2 + e2] + (e2 ? bhr.y : bhr.x);
                            const float ghz = acc[1][mt][nt][eh * 2 + e2] + (e2 ? bhz.y : bhz.x);
                            const float ghn = acc[2][mt][nt][eh * 2 + e2] + (e2 ? bhn.y : bhn.x);
                            const float rg = fsig((e2 ? gr.y : gr.x) + ghr);
                            const float zg = fsig((e2 ? gz.y : gz.x) + ghz);
                            const float ng = ftanhf((e2 ? gn.y : gn.x) + rg * ghn);
                            const float ho = e2 ? hof.y : hof.x;
                            (e2 ? hv.y : hv.x) = (1.f - zg) * ng + zg * ho;
                        }
                        if (t == KS_ - 1) {
                            *(float2*)(out + (size_t)chain * D_ + dwg) = hv;
                        } else {
                            __half2 hx = __floats2half2_rn(hv.x, hv.y);
                            Hnxt[row * HW_S + hw] = *(uint32_t*)&hx;
                        }
                    }
            }
        }

        if (t < KS_ - 1) __syncthreads();   // Hnxt complete before next step reads
    }
}

// ---------------------------------------------------------------------------
// Launch — gi first (ncu capture lands on the first launch)
// ---------------------------------------------------------------------------
extern "C" void kernel_launch(void* const* d_in, const int* in_sizes, int n_in,
                              void* d_out, int out_size)
{
    const float* x   = (const float*)d_in[0];
    const float* Wih = (const float*)d_in[1];
    const float* Whh = (const float*)d_in[2];
    const float* bih = (const float*)d_in[3];
    const float* bhh = (const float*)d_in[4];
    float* out = (float*)d_out;

    cudaFuncSetAttribute(gi_mma_kernel,
                         cudaFuncAttributeMaxDynamicSharedMemorySize, GI_SMEM_BYTES);
    dim3 gi_grid(NCH_ / 128, G_ / 128);
    gi_mma_kernel<<<gi_grid, 256, GI_SMEM_BYTES>>>(x, Wih, bih);

    wprep_kernel<<<384, 256>>>(Whh);

    cudaFuncSetAttribute(rnn_mma_kernel,
                         cudaFuncAttributeMaxDynamicSharedMemorySize, RNN_SMEM_BYTES);
    rnn_mma_kernel<<<128, 256, RNN_SMEM_BYTES>>>(bih, bhh, out);
}

// round 13
// speedup vs baseline: 3.0135x; 1.1567x over previous
#include <cuda_runtime.h>
#include <cuda_fp16.h>
#include <stdint.h>
#include <math.h>

// LocalRNN: B=16, L=1024, D=256, ksize=16
#define B_   16
#define L_   1024
#define D_   256
#define KS_  16
#define G_   768
#define NCH_ (B_ * L_)

// Static device scratch
__device__ float    g_gi[(size_t)NCH_ * G_];   // gi[chain][gate_dim]
__device__ uint32_t g_wh[98304];               // W_hh fp16 half2, fragment order (384KB)

__device__ __forceinline__ float tanha(float x) {
    float y; asm("tanh.approx.f32 %0, %1;" : "=f"(y) : "f"(x)); return y;
}
__device__ __forceinline__ float fsig(float x)   { return fmaf(0.5f, tanha(0.5f * x), 0.5f); }
__device__ __forceinline__ float ftanhf(float x) { return __fdividef(2.f, 1.f + __expf(-2.f * x)) - 1.f; }
// paired-word permutation: pairs (w, w+4) adjacent within each 8-group
__device__ __forceinline__ int permw(int w) {
    return (w & ~7) | ((w & 3) << 1) | ((w >> 2) & 1);
}
__device__ __forceinline__ int hword(int d) { return permw(d >> 1); }

__device__ __forceinline__ void mma16f(float* d, const uint32_t* a, uint32_t b0, uint32_t b1) {
    asm volatile(
        "mma.sync.aligned.m16n8k16.row.col.f32.f16.f16.f32 "
        "{%0,%1,%2,%3}, {%4,%5,%6,%7}, {%8,%9}, {%0,%1,%2,%3};"
        : "+f"(d[0]), "+f"(d[1]), "+f"(d[2]), "+f"(d[3])
        : "r"(a[0]), "r"(a[1]), "r"(a[2]), "r"(a[3]), "r"(b0), "r"(b1));
}

// ---------------------------------------------------------------------------
// Prep: W_hh -> fp16 half2, m16n8k16 fragment order (slab = c*4+kq, 6144 w).
// ---------------------------------------------------------------------------
__global__ void wprep_kernel(const float* __restrict__ Whh) {
    int e = blockIdx.x * 256 + threadIdx.x;
    if (e >= 98304) return;
    int slab = e / 6144, w6 = e % 6144;
    int c = slab >> 2, kq = slab & 3;
    int block = w6 / 768, rem = w6 % 768;
    int g = rem >> 8;
    int r2 = rem & 255;
    int nt2 = r2 >> 7;
    int rr = r2 & 127;
    int lane = rr >> 2, o = rr & 3;
    int nt = nt2 * 2 + (o >> 1), r = o & 1;
    int k16m = block & 3, ncol = block >> 2;
    int k   = kq * 64 + k16m * 16 + 2 * (lane & 3) + r * 8;
    int dim = ncol * 128 + c * 32 + nt * 8 + (lane >> 2);
    const float* wr = Whh + (size_t)(g * 256 + dim) * D_ + k;
    __half2 h2 = __floats2half2_rn(wr[0], wr[1]);
    g_wh[e] = *(uint32_t*)&h2;
}

// ---------------------------------------------------------------------------
// gi = x @ W_ih^T + b_ih via fp16 mma. grid (256, 6), 256 thr, 2 CTAs/SM.
// CTA tile: 64 chains x 128 gate-dims. X + Wih staged once; barrier-free loop.
// ---------------------------------------------------------------------------
#define GXW_S 136
#define GI_XS_W (64 * GXW_S)             // 8704
#define GI_WS_W 16384
#define GI_SMEM_BYTES ((GI_XS_W + GI_WS_W) * 4)   // 100352 B

__global__ __launch_bounds__(256) void gi_mma_kernel(
    const float* __restrict__ x,
    const float* __restrict__ Wih,
    const float* __restrict__ bih)
{
    extern __shared__ uint32_t gsm[];
    uint32_t* Xs  = gsm;
    uint32_t* Wst = gsm + GI_XS_W;

    const int tid = threadIdx.x;
    const int lane = tid & 31, wid = tid >> 5;
    const int qrow = lane >> 2, qcol = lane & 3;
    const int mbase = (wid & 3) * 16;
    const int ncol  = wid >> 2;
    const int mt0 = blockIdx.x * 64;
    const int ntile = blockIdx.y * 128;

    {   // stage X: row = tid>>2, quarter = tid&3 (64 floats -> 32 half2 words)
        const int row = tid >> 2, q = tid & 3;
        const float* xp = x + (size_t)(mt0 + row) * D_ + q * 64;
        uint32_t* xr = Xs + row * GXW_S;
#pragma unroll
        for (int i = 0; i < 8; i++) {
            float4 v0 = *(const float4*)(xp + i * 8);
            float4 v1 = *(const float4*)(xp + i * 8 + 4);
            const int w0 = q * 32 + i * 4;
            __half2 p0 = __floats2half2_rn(v0.x, v0.y);
            __half2 p1 = __floats2half2_rn(v0.z, v0.w);
            __half2 p2 = __floats2half2_rn(v1.x, v1.y);
            __half2 p3 = __floats2half2_rn(v1.z, v1.w);
            xr[permw(w0 + 0)] = *(uint32_t*)&p0;
            xr[permw(w0 + 1)] = *(uint32_t*)&p1;
            xr[permw(w0 + 2)] = *(uint32_t*)&p2;
            xr[permw(w0 + 3)] = *(uint32_t*)&p3;
        }
    }
    {   // stage Wih tile in fragment order: gd = tid>>1, k-half = tid&1
        const int gd = tid >> 1, half = tid & 1;
        const float* wp = Wih + (size_t)(ntile + gd) * D_ + half * 128;
        const int base = (gd >> 3) * 64 + ((gd & 7) << 3);
#pragma unroll
        for (int i = 0; i < 16; i++) {
            float4 v0 = *(const float4*)(wp + i * 8);
            float4 v1 = *(const float4*)(wp + i * 8 + 4);
            const float vv[8] = {v0.x, v0.y, v0.z, v0.w, v1.x, v1.y, v1.z, v1.w};
#pragma unroll
            for (int j = 0; j < 4; j++) {
                const int k = half * 128 + i * 8 + 2 * j;
                __half2 h2 = __floats2half2_rn(vv[2 * j], vv[2 * j + 1]);
                const int word = (k >> 4) * 1024 + base + (((k >> 1) & 3) << 1) + ((k >> 3) & 1);
                Wst[word] = *(uint32_t*)&h2;
            }
        }
    }
    __syncthreads();

    float acc[8][4];
#pragma unroll
    for (int nt = 0; nt < 8; nt++)
#pragma unroll
        for (int e = 0; e < 4; e++) acc[nt][e] = 0.f;

#pragma unroll
    for (int k16 = 0; k16 < 16; k16++) {
        const int ko = k16 * 8 + 2 * qcol;
        uint32_t a[4];
        {
            uint2 lo = *(const uint2*)(Xs + (mbase + qrow) * GXW_S + ko);
            uint2 hi = *(const uint2*)(Xs + (mbase + 8 + qrow) * GXW_S + ko);
            a[0] = lo.x; a[1] = hi.x; a[2] = lo.y; a[3] = hi.y;
        }
        const uint32_t* wb = Wst + k16 * 1024 + ncol * 512 + lane * 2;
#pragma unroll
        for (int nt = 0; nt < 8; nt++) {
            uint2 b = *(const uint2*)(wb + nt * 64);
            mma16f(acc[nt], a, b.x, b.y);
        }
    }

#pragma unroll
    for (int nt = 0; nt < 8; nt++) {
        const int gd = ntile + ncol * 64 + nt * 8 + 2 * qcol;
        const float2 bv = *(const float2*)(bih + gd);
#pragma unroll
        for (int eh = 0; eh < 2; eh++) {
            const int chain = mt0 + mbase + eh * 8 + qrow;
            float2 o;
            o.x = acc[nt][eh * 2 + 0] + bv.x;
            o.y = acc[nt][eh * 2 + 1] + bv.y;
            *(float2*)(g_gi + (size_t)chain * G_ + gd) = o;
        }
    }
}

// ---------------------------------------------------------------------------
// Main recurrence, fp16 m16n8k16, 512 threads (16 warps: 8M x 2Ncol),
// double-buffered H in smem. 128 CTAs x 128 chains.
// ---------------------------------------------------------------------------
#define HW_S   136
#define HBUF_W (128 * HW_S)             // 17408
#define WSLAB  6144
#define SMF_WS  (2 * HBUF_W)            // 34816
#define SMF_BIH (SMF_WS + 2 * WSLAB)    // 47104
#define SMF_BHH (SMF_BIH + G_)
#define RNN_SMEM_BYTES ((SMF_BHH + G_) * 4)   // 194560 B

__global__ __launch_bounds__(512, 1) void rnn_mma_kernel(
    const float* __restrict__ bih_g,
    const float* __restrict__ bhh_g,
    float* __restrict__ out)
{
    extern __shared__ uint32_t sm[];
    uint32_t* Ws_u  = sm + SMF_WS;
    float*    bih_s = (float*)(sm + SMF_BIH);
    float*    bhh_s = (float*)(sm + SMF_BHH);

    const int tid = threadIdx.x;
    const int lane = tid & 31, wid = tid >> 5;
    const int qrow = lane >> 2, qcol = lane & 3;
    const int mbase = (wid & 7) * 16;
    const int ncol  = wid >> 3;
    const int n0 = blockIdx.x * 128;

    for (int i = tid * 4; i < HBUF_W; i += 2048)
        *(uint4*)(sm + i) = make_uint4(0, 0, 0, 0);
    for (int i = tid; i < G_; i += 512) { bih_s[i] = bih_g[i]; bhh_s[i] = bhh_g[i]; }

    uint4 pf[3];
    {   // slab0 -> buf0, prefetch slab1
        const uint4* s = (const uint4*)g_wh;
#pragma unroll
        for (int j = 0; j < 3; j++) pf[j] = s[tid + j * 512];
        uint4* d = (uint4*)Ws_u;
#pragma unroll
        for (int j = 0; j < 3; j++) d[tid + j * 512] = pf[j];
#pragma unroll
        for (int j = 0; j < 3; j++) pf[j] = s[1536 + tid + j * 512];
    }
    __syncthreads();

    int sc = 0;   // slab phase counter (slab = sc & 15)

    for (int t = 0; t < KS_; t++) {
        uint32_t* Hcur = sm + (t & 1) * HBUF_W;
        uint32_t* Hnxt = sm + ((t + 1) & 1) * HBUF_W;

        for (int c = 0; c < 4; c++) {
            float acc[3][4][4];
#pragma unroll
            for (int g = 0; g < 3; g++)
#pragma unroll
                for (int nt = 0; nt < 4; nt++)
#pragma unroll
                    for (int e = 0; e < 4; e++) acc[g][nt][e] = 0.f;

            for (int kq = 0; kq < 4; kq++) {
                const uint32_t* W = Ws_u + (sc & 1) * WSLAB;
                {   // commit next slab (regs -> other buffer), overlaps MMA
                    uint4* d = (uint4*)(Ws_u + ((sc + 1) & 1) * WSLAB);
#pragma unroll
                    for (int j = 0; j < 3; j++) d[tid + j * 512] = pf[j];
                }
                {   // prefetch slab sc+2
                    const uint4* s = ((const uint4*)g_wh)
                                   + (size_t)((sc + 2) & 15) * (WSLAB / 4);
#pragma unroll
                    for (int j = 0; j < 3; j++) pf[j] = s[tid + j * 512];
                }

#pragma unroll
                for (int k16m = 0; k16m < 4; k16m++) {
                    const int k16 = kq * 4 + k16m;
                    const int ko  = k16 * 8 + 2 * qcol;
                    uint32_t a[4];
                    {
                        uint2 lo = *(const uint2*)(Hcur + (mbase + qrow) * HW_S + ko);
                        uint2 hi = *(const uint2*)(Hcur + (mbase + 8 + qrow) * HW_S + ko);
                        a[0] = lo.x; a[1] = hi.x; a[2] = lo.y; a[3] = hi.y;
                    }
                    const uint32_t* wk = W + (ncol * 4 + k16m) * 768 + lane * 4;
#pragma unroll
                    for (int g = 0; g < 3; g++)
#pragma unroll
                        for (int nt2 = 0; nt2 < 2; nt2++) {
                            uint4 bv = *(const uint4*)(wk + g * 256 + nt2 * 128);
                            mma16f(acc[g][nt2 * 2 + 0], a, bv.x, bv.y);
                            mma16f(acc[g][nt2 * 2 + 1], a, bv.z, bv.w);
                        }
                }
                __syncthreads();
                sc++;
            }

            // ---- fused GRU epilogue for chunk c (32 dims per warp-col) ----
#pragma unroll
            for (int nt = 0; nt < 4; nt++) {
                const int dwg = ncol * 128 + c * 32 + nt * 8 + 2 * qcol;
                const float2 bhr = *(const float2*)(bhh_s + dwg);
                const float2 bhz = *(const float2*)(bhh_s + 256 + dwg);
                const float2 bhn = *(const float2*)(bhh_s + 512 + dwg);
                const int hw = hword(dwg);
#pragma unroll
                for (int eh = 0; eh < 2; eh++) {
                    const int row   = mbase + eh * 8 + qrow;
                    const int chain = n0 + row;
                    const int lp    = (chain & (L_ - 1)) - (KS_ - 1) + t;
                    float2 gr, gz, gn;
                    if (lp >= 0) {
                        const float* gp = g_gi + (size_t)(chain - (KS_ - 1) + t) * G_;
                        gr = *(const float2*)(gp + dwg);
                        gz = *(const float2*)(gp + 256 + dwg);
                        gn = *(const float2*)(gp + 512 + dwg);
                    } else {
                        gr = *(const float2*)(bih_s + dwg);
                        gz = *(const float2*)(bih_s + 256 + dwg);
                        gn = *(const float2*)(bih_s + 512 + dwg);
                    }
                    const __half2 hh = *(const __half2*)(Hcur + row * HW_S + hw);
                    const float2 hof = __half22float2(hh);
                    float2 hv;
#pragma unroll
                    for (int e2 = 0; e2 < 2; e2++) {
                        const float ghr = acc[0][nt][eh * 2 + e2] + (e2 ? bhr.y : bhr.x);
                        const float ghz = acc[1][nt][eh * 2 + e2] + (e2 ? bhz.y : bhz.x);
                        const float ghn = acc[2][nt][eh * 2 + e2] + (e2 ? bhn.y : bhn.x);
                        const float rg = fsig((e2 ? gr.y : gr.x) + ghr);
                        const float zg = fsig((e2 ? gz.y : gz.x) + ghz);
                        const float ng = ftanhf((e2 ? gn.y : gn.x) + rg * ghn);
                        const float ho = e2 ? hof.y : hof.x;
                        (e2 ? hv.y : hv.x) = (1.f - zg) * ng + zg * ho;
                    }
                    if (t == KS_ - 1) {
                        *(float2*)(out + (size_t)chain * D_ + dwg) = hv;
                    } else {
                        __half2 hx = __floats2half2_rn(hv.x, hv.y);
                        Hnxt[row * HW_S + hw] = *(uint32_t*)&hx;
                    }
                }
            }
        }

        if (t < KS_ - 1) __syncthreads();   // Hnxt complete before next step reads
    }
}

// ---------------------------------------------------------------------------
// Launch — gi first (ncu capture lands on the first launch)
// ---------------------------------------------------------------------------
extern "C" void kernel_launch(void* const* d_in, const int* in_sizes, int n_in,
                              void* d_out, int out_size)
{
    const float* x   = (const float*)d_in[0];
    const float* Wih = (const float*)d_in[1];
    const float* Whh = (const float*)d_in[2];
    const float* bih = (const float*)d_in[3];
    const float* bhh = (const float*)d_in[4];
    float* out = (float*)d_out;

    cudaFuncSetAttribute(gi_mma_kernel,
                         cudaFuncAttributeMaxDynamicSharedMemorySize, GI_SMEM_BYTES);
    dim3 gi_grid(NCH_ / 64, G_ / 128);
    gi_mma_kernel<<<gi_grid, 256, GI_SMEM_BYTES>>>(x, Wih, bih);

    wprep_kernel<<<384, 256>>>(Whh);

    cudaFuncSetAttribute(rnn_mma_kernel,
                         cudaFuncAttributeMaxDynamicSharedMemorySize, RNN_SMEM_BYTES);
    rnn_mma_kernel<<<128, 512, RNN_SMEM_BYTES>>>(bih, bhh, out);
}

// round 14
// speedup vs baseline: 3.6884x; 1.2240x over previous
#include <cuda_runtime.h>
#include <cuda_fp16.h>
#include <stdint.h>
#include <math.h>

// LocalRNN: B=16, L=1024, D=256, ksize=16
#define B_   16
#define L_   1024
#define D_   256
#define KS_  16
#define G_   768
#define NCH_ (B_ * L_)

// Static device scratch
__device__ float    g_gi[(size_t)NCH_ * G_];   // gi[chain][gate_dim]
__device__ uint32_t g_wh[98304];               // W_hh fp16, rnn fragment order (384KB)
__device__ uint32_t g_wih[98304];              // W_ih fp16, gi B-fragment order (384KB)
__device__ uint4    g_xh[524288];              // x fp16, gi A-fragment order (8MB)

__device__ __forceinline__ float tanha(float x) {
    float y; asm("tanh.approx.f32 %0, %1;" : "=f"(y) : "f"(x)); return y;
}
__device__ __forceinline__ float fsig(float x) { return fmaf(0.5f, tanha(0.5f * x), 0.5f); }
// paired-word permutation (rnn H layout)
__device__ __forceinline__ int permw(int w) {
    return (w & ~7) | ((w & 3) << 1) | ((w >> 2) & 1);
}
__device__ __forceinline__ int hword(int d) { return permw(d >> 1); }

__device__ __forceinline__ void mma16f(float* d, const uint32_t* a, uint32_t b0, uint32_t b1) {
    asm volatile(
        "mma.sync.aligned.m16n8k16.row.col.f32.f16.f16.f32 "
        "{%0,%1,%2,%3}, {%4,%5,%6,%7}, {%8,%9}, {%0,%1,%2,%3};"
        : "+f"(d[0]), "+f"(d[1]), "+f"(d[2]), "+f"(d[3])
        : "r"(a[0]), "r"(a[1]), "r"(a[2]), "r"(a[3]), "r"(b0), "r"(b1));
}

// ---------------------------------------------------------------------------
// Merged prep: W_hh frag (98304 w) | W_ih frag (98304 w) | x A-frag (524288 uint4)
// grid 2816 x 256.
// ---------------------------------------------------------------------------
__global__ void prep_kernel(const float* __restrict__ x,
                            const float* __restrict__ Wih,
                            const float* __restrict__ Whh)
{
    int e = blockIdx.x * 256 + threadIdx.x;
    if (e < 98304) {
        // W_hh -> rnn fragment order (slab = c*4+kq, 6144 words)
        int slab = e / 6144, w6 = e % 6144;
        int c = slab >> 2, kq = slab & 3;
        int block = w6 / 768, rem = w6 % 768;
        int g = rem >> 8;
        int r2 = rem & 255;
        int nt2 = r2 >> 7;
        int rr = r2 & 127;
        int lane = rr >> 2, o = rr & 3;
        int nt = nt2 * 2 + (o >> 1), r = o & 1;
        int k16m = block & 3, ncol = block >> 2;
        int k   = kq * 64 + k16m * 16 + 2 * (lane & 3) + r * 8;
        int dim = ncol * 128 + c * 32 + nt * 8 + (lane >> 2);
        const float* wr = Whh + (size_t)(g * 256 + dim) * D_ + k;
        __half2 h2 = __floats2half2_rn(wr[0], wr[1]);
        g_wh[e] = *(uint32_t*)&h2;
    } else if (e < 196608) {
        // W_ih -> gi B-fragment order: e2 = ntile*16384 + k16*1024 + ncol*512
        //                                  + nt*64 + lane*2 + r
        int e2 = e - 98304;
        int r = e2 & 1, lane = (e2 >> 1) & 31;
        int nt = (e2 >> 6) & 7, ncol = (e2 >> 9) & 1;
        int k16 = (e2 >> 10) & 15, ntile = e2 >> 14;
        int qrow = lane >> 2, qcol = lane & 3;
        int gd = ntile * 128 + ncol * 64 + nt * 8 + qrow;
        int k  = k16 * 16 + 2 * qcol + r * 8;
        const float* wr = Wih + (size_t)gd * D_ + k;
        __half2 h2 = __floats2half2_rn(wr[0], wr[1]);
        g_wih[e2] = *(uint32_t*)&h2;
    } else {
        // x -> A-fragment image: e3 = ((cb*16 + k16)*8 + mgroup)*32 + lane
        int e3 = e - 196608;
        if (e3 >= 524288) return;
        int lane = e3 & 31, mgroup = (e3 >> 5) & 7;
        int k16 = (e3 >> 8) & 15, cb = e3 >> 12;
        int qrow = lane >> 2, qcol = lane & 3;
        int r0 = cb * 128 + mgroup * 16 + qrow, r1 = r0 + 8;
        int kb = k16 * 16 + 2 * qcol;
        const float* x0 = x + (size_t)r0 * D_ + kb;
        const float* x1 = x + (size_t)r1 * D_ + kb;
        __half2 w0 = __floats2half2_rn(x0[0], x0[1]);
        __half2 w1 = __floats2half2_rn(x1[0], x1[1]);
        __half2 w2 = __floats2half2_rn(x0[8], x0[9]);
        __half2 w3 = __floats2half2_rn(x1[8], x1[9]);
        uint4 v;
        v.x = *(uint32_t*)&w0; v.y = *(uint32_t*)&w1;
        v.z = *(uint32_t*)&w2; v.w = *(uint32_t*)&w3;
        g_xh[e3] = v;
    }
}

// ---------------------------------------------------------------------------
// gi = x @ W_ih^T + b_ih via fp16 mma. grid (128, 6), 256 thr, 8 warps
// (4M x 2Ncol). W staged linearly into 64KB smem (one barrier); A-frags
// software-pipelined LDG.128 straight from the fragment image (no X smem).
// ---------------------------------------------------------------------------
#define GI_WS_W 16384
#define GI_SMEM_BYTES (GI_WS_W * 4)      // 65536 B

__global__ __launch_bounds__(256) void gi_mma_kernel(
    const float* __restrict__ bih)
{
    extern __shared__ uint32_t Wst[];

    const int tid = threadIdx.x;
    const int lane = tid & 31, wid = tid >> 5;
    const int qrow = lane >> 2, qcol = lane & 3;
    const int mwarp = wid & 3;
    const int ncol  = wid >> 2;
    const int cb = blockIdx.x;
    const int ntile = blockIdx.y;

    {   // stage Wih tile: pure linear copy from fragment image
        const uint4* ws = ((const uint4*)g_wih) + ntile * 4096;
        uint4* wd = (uint4*)Wst;
#pragma unroll
        for (int j = 0; j < 16; j++) wd[tid + j * 256] = ws[tid + j * 256];
    }
    __syncthreads();

    float acc[2][8][4];
#pragma unroll
    for (int mt = 0; mt < 2; mt++)
#pragma unroll
        for (int nt = 0; nt < 8; nt++)
#pragma unroll
            for (int e = 0; e < 4; e++) acc[mt][nt][e] = 0.f;

    const uint4* xp = g_xh + (size_t)cb * 4096;
    uint4 apf[2];
    apf[0] = xp[(mwarp * 2 + 0) * 32 + lane];
    apf[1] = xp[(mwarp * 2 + 1) * 32 + lane];

#pragma unroll
    for (int k16 = 0; k16 < 16; k16++) {
        uint4 a0 = apf[0], a1 = apf[1];
        if (k16 < 15) {
            apf[0] = xp[((k16 + 1) * 8 + mwarp * 2 + 0) * 32 + lane];
            apf[1] = xp[((k16 + 1) * 8 + mwarp * 2 + 1) * 32 + lane];
        }
        const uint32_t* wb = Wst + k16 * 1024 + ncol * 512 + lane * 2;
#pragma unroll
        for (int nt = 0; nt < 8; nt++) {
            uint2 b = *(const uint2*)(wb + nt * 64);
            mma16f(acc[0][nt], (const uint32_t*)&a0, b.x, b.y);
            mma16f(acc[1][nt], (const uint32_t*)&a1, b.x, b.y);
        }
    }

#pragma unroll
    for (int nt = 0; nt < 8; nt++) {
        const int gd = ntile * 128 + ncol * 64 + nt * 8 + 2 * qcol;
        const float2 bv = *(const float2*)(bih + gd);
#pragma unroll
        for (int mt = 0; mt < 2; mt++)
#pragma unroll
            for (int eh = 0; eh < 2; eh++) {
                const int chain = cb * 128 + mwarp * 32 + mt * 16 + eh * 8 + qrow;
                float2 o;
                o.x = acc[mt][nt][eh * 2 + 0] + bv.x;
                o.y = acc[mt][nt][eh * 2 + 1] + bv.y;
                *(float2*)(g_gi + (size_t)chain * G_ + gd) = o;
            }
    }
}

// ---------------------------------------------------------------------------
// Main recurrence, fp16 m16n8k16, 512 threads (16 warps: 8M x 2Ncol),
// double-buffered H in smem. 128 CTAs x 128 chains.
// ---------------------------------------------------------------------------
#define HW_S   136
#define HBUF_W (128 * HW_S)             // 17408
#define WSLAB  6144
#define SMF_WS  (2 * HBUF_W)            // 34816
#define SMF_BIH (SMF_WS + 2 * WSLAB)    // 47104
#define SMF_BHH (SMF_BIH + G_)
#define RNN_SMEM_BYTES ((SMF_BHH + G_) * 4)   // 194560 B

__global__ __launch_bounds__(512, 1) void rnn_mma_kernel(
    const float* __restrict__ bih_g,
    const float* __restrict__ bhh_g,
    float* __restrict__ out)
{
    extern __shared__ uint32_t sm[];
    uint32_t* Ws_u  = sm + SMF_WS;
    float*    bih_s = (float*)(sm + SMF_BIH);
    float*    bhh_s = (float*)(sm + SMF_BHH);

    const int tid = threadIdx.x;
    const int lane = tid & 31, wid = tid >> 5;
    const int qrow = lane >> 2, qcol = lane & 3;
    const int mbase = (wid & 7) * 16;
    const int ncol  = wid >> 3;
    const int n0 = blockIdx.x * 128;

    for (int i = tid * 4; i < HBUF_W; i += 2048)
        *(uint4*)(sm + i) = make_uint4(0, 0, 0, 0);
    for (int i = tid; i < G_; i += 512) { bih_s[i] = bih_g[i]; bhh_s[i] = bhh_g[i]; }

    uint4 pf[3];
    {   // slab0 -> buf0, prefetch slab1
        const uint4* s = (const uint4*)g_wh;
#pragma unroll
        for (int j = 0; j < 3; j++) pf[j] = s[tid + j * 512];
        uint4* d = (uint4*)Ws_u;
#pragma unroll
        for (int j = 0; j < 3; j++) d[tid + j * 512] = pf[j];
#pragma unroll
        for (int j = 0; j < 3; j++) pf[j] = s[1536 + tid + j * 512];
    }
    __syncthreads();

    int sc = 0;   // slab phase counter (slab = sc & 15)

    for (int t = 0; t < KS_; t++) {
        uint32_t* Hcur = sm + (t & 1) * HBUF_W;
        uint32_t* Hnxt = sm + ((t + 1) & 1) * HBUF_W;

        for (int c = 0; c < 4; c++) {
            float acc[3][4][4];
#pragma unroll
            for (int g = 0; g < 3; g++)
#pragma unroll
                for (int nt = 0; nt < 4; nt++)
#pragma unroll
                    for (int e = 0; e < 4; e++) acc[g][nt][e] = 0.f;

            for (int kq = 0; kq < 4; kq++) {
                const uint32_t* W = Ws_u + (sc & 1) * WSLAB;
                {   // commit next slab (regs -> other buffer), overlaps MMA
                    uint4* d = (uint4*)(Ws_u + ((sc + 1) & 1) * WSLAB);
#pragma unroll
                    for (int j = 0; j < 3; j++) d[tid + j * 512] = pf[j];
                }
                {   // prefetch slab sc+2
                    const uint4* s = ((const uint4*)g_wh)
                                   + (size_t)((sc + 2) & 15) * (WSLAB / 4);
#pragma unroll
                    for (int j = 0; j < 3; j++) pf[j] = s[tid + j * 512];
                }

#pragma unroll
                for (int k16m = 0; k16m < 4; k16m++) {
                    const int k16 = kq * 4 + k16m;
                    const int ko  = k16 * 8 + 2 * qcol;
                    uint32_t a[4];
                    {
                        uint2 lo = *(const uint2*)(Hcur + (mbase + qrow) * HW_S + ko);
                        uint2 hi = *(const uint2*)(Hcur + (mbase + 8 + qrow) * HW_S + ko);
                        a[0] = lo.x; a[1] = hi.x; a[2] = lo.y; a[3] = hi.y;
                    }
                    const uint32_t* wk = W + (ncol * 4 + k16m) * 768 + lane * 4;
#pragma unroll
                    for (int g = 0; g < 3; g++)
#pragma unroll
                        for (int nt2 = 0; nt2 < 2; nt2++) {
                            uint4 bv = *(const uint4*)(wk + g * 256 + nt2 * 128);
                            mma16f(acc[g][nt2 * 2 + 0], a, bv.x, bv.y);
                            mma16f(acc[g][nt2 * 2 + 1], a, bv.z, bv.w);
                        }
                }
                __syncthreads();
                sc++;
            }

            // ---- fused GRU epilogue for chunk c (32 dims per warp-col) ----
#pragma unroll
            for (int nt = 0; nt < 4; nt++) {
                const int dwg = ncol * 128 + c * 32 + nt * 8 + 2 * qcol;
                const float2 bhr = *(const float2*)(bhh_s + dwg);
                const float2 bhz = *(const float2*)(bhh_s + 256 + dwg);
                const float2 bhn = *(const float2*)(bhh_s + 512 + dwg);
                const int hw = hword(dwg);
#pragma unroll
                for (int eh = 0; eh < 2; eh++) {
                    const int row   = mbase + eh * 8 + qrow;
                    const int chain = n0 + row;
                    const int lp    = (chain & (L_ - 1)) - (KS_ - 1) + t;
                    float2 gr, gz, gn;
                    if (lp >= 0) {
                        const float* gp = g_gi + (size_t)(chain - (KS_ - 1) + t) * G_;
                        gr = *(const float2*)(gp + dwg);
                        gz = *(const float2*)(gp + 256 + dwg);
                        gn = *(const float2*)(gp + 512 + dwg);
                    } else {
                        gr = *(const float2*)(bih_s + dwg);
                        gz = *(const float2*)(bih_s + 256 + dwg);
                        gn = *(const float2*)(bih_s + 512 + dwg);
                    }
                    const __half2 hh = *(const __half2*)(Hcur + row * HW_S + hw);
                    const float2 hof = __half22float2(hh);
                    float2 hv;
#pragma unroll
                    for (int e2 = 0; e2 < 2; e2++) {
                        const float ghr = acc[0][nt][eh * 2 + e2] + (e2 ? bhr.y : bhr.x);
                        const float ghz = acc[1][nt][eh * 2 + e2] + (e2 ? bhz.y : bhz.x);
                        const float ghn = acc[2][nt][eh * 2 + e2] + (e2 ? bhn.y : bhn.x);
                        const float rg = fsig((e2 ? gr.y : gr.x) + ghr);
                        const float zg = fsig((e2 ? gz.y : gz.x) + ghz);
                        const float ng = tanha((e2 ? gn.y : gn.x) + rg * ghn);
                        const float ho = e2 ? hof.y : hof.x;
                        (e2 ? hv.y : hv.x) = (1.f - zg) * ng + zg * ho;
                    }
                    if (t == KS_ - 1) {
                        *(float2*)(out + (size_t)chain * D_ + dwg) = hv;
                    } else {
                        __half2 hx = __floats2half2_rn(hv.x, hv.y);
                        Hnxt[row * HW_S + hw] = *(uint32_t*)&hx;
                    }
                }
            }
        }

        if (t < KS_ - 1) __syncthreads();   // Hnxt complete before next step reads
    }
}

// ---------------------------------------------------------------------------
// Launch: prep -> gi -> rnn
// ---------------------------------------------------------------------------
extern "C" void kernel_launch(void* const* d_in, const int* in_sizes, int n_in,
                              void* d_out, int out_size)
{
    const float* x   = (const float*)d_in[0];
    const float* Wih = (const float*)d_in[1];
    const float* Whh = (const float*)d_in[2];
    const float* bih = (const float*)d_in[3];
    const float* bhh = (const float*)d_in[4];
    float* out = (float*)d_out;

    prep_kernel<<<2816, 256>>>(x, Wih, Whh);

    cudaFuncSetAttribute(gi_mma_kernel,
                         cudaFuncAttributeMaxDynamicSharedMemorySize, GI_SMEM_BYTES);
    dim3 gi_grid(NCH_ / 128, G_ / 128);
    gi_mma_kernel<<<gi_grid, 256, GI_SMEM_BYTES>>>(bih);

    cudaFuncSetAttribute(rnn_mma_kernel,
                         cudaFuncAttributeMaxDynamicSharedMemorySize, RNN_SMEM_BYTES);
    rnn_mma_kernel<<<128, 512, RNN_SMEM_BYTES>>>(bih, bhh, out);
}

// round 15
// speedup vs baseline: 3.7348x; 1.0126x over previous
#include <cuda_runtime.h>
#include <cuda_fp16.h>
#include <stdint.h>
#include <math.h>

// LocalRNN: B=16, L=1024, D=256, ksize=16
#define B_   16
#define L_   1024
#define D_   256
#define KS_  16
#define G_   768
#define NCH_ (B_ * L_)

// Static device scratch
__device__ uint32_t g_gih[(size_t)NCH_ * 384];  // gi[chain] packed half2 (25MB)
__device__ uint32_t g_wh[98304];                // W_hh fp16, rnn fragment order
__device__ uint32_t g_wih[98304];               // W_ih fp16, gi B-fragment order
__device__ uint4    g_xh[524288];               // x fp16, gi A-fragment order (8MB)

__device__ __forceinline__ __half2 tanh2(__half2 x) {
    __half2 y;
    asm("tanh.approx.f16x2 %0, %1;" : "=r"(*(uint32_t*)&y) : "r"(*(uint32_t*)&x));
    return y;
}
__device__ __forceinline__ __half2 sig2(__half2 x) {
    const __half2 h05 = __float2half2_rn(0.5f);
    return __hfma2(tanh2(__hmul2(x, h05)), h05, h05);
}
// paired-word permutation (rnn H layout)
__device__ __forceinline__ int permw(int w) {
    return (w & ~7) | ((w & 3) << 1) | ((w >> 2) & 1);
}
__device__ __forceinline__ int hword(int d) { return permw(d >> 1); }

__device__ __forceinline__ void mma16f(float* d, const uint32_t* a, uint32_t b0, uint32_t b1) {
    asm volatile(
        "mma.sync.aligned.m16n8k16.row.col.f32.f16.f16.f32 "
        "{%0,%1,%2,%3}, {%4,%5,%6,%7}, {%8,%9}, {%0,%1,%2,%3};"
        : "+f"(d[0]), "+f"(d[1]), "+f"(d[2]), "+f"(d[3])
        : "r"(a[0]), "r"(a[1]), "r"(a[2]), "r"(a[3]), "r"(b0), "r"(b1));
}

// ---------------------------------------------------------------------------
// Merged prep: W_hh frag | W_ih frag | x A-frag. grid 2816 x 256.
// ---------------------------------------------------------------------------
__global__ void prep_kernel(const float* __restrict__ x,
                            const float* __restrict__ Wih,
                            const float* __restrict__ Whh)
{
    int e = blockIdx.x * 256 + threadIdx.x;
    if (e < 98304) {
        // W_hh -> rnn fragment order (slab = c*4+kq, 6144 words)
        int slab = e / 6144, w6 = e % 6144;
        int c = slab >> 2, kq = slab & 3;
        int block = w6 / 768, rem = w6 % 768;
        int g = rem >> 8;
        int r2 = rem & 255;
        int nt2 = r2 >> 7;
        int rr = r2 & 127;
        int lane = rr >> 2, o = rr & 3;
        int nt = nt2 * 2 + (o >> 1), r = o & 1;
        int k16m = block & 3, ncol = block >> 2;
        int k   = kq * 64 + k16m * 16 + 2 * (lane & 3) + r * 8;
        int dim = ncol * 128 + c * 32 + nt * 8 + (lane >> 2);
        const float* wr = Whh + (size_t)(g * 256 + dim) * D_ + k;
        __half2 h2 = __floats2half2_rn(wr[0], wr[1]);
        g_wh[e] = *(uint32_t*)&h2;
    } else if (e < 196608) {
        // W_ih -> gi B-fragment order
        int e2 = e - 98304;
        int r = e2 & 1, lane = (e2 >> 1) & 31;
        int nt = (e2 >> 6) & 7, ncol = (e2 >> 9) & 1;
        int k16 = (e2 >> 10) & 15, ntile = e2 >> 14;
        int qrow = lane >> 2, qcol = lane & 3;
        int gd = ntile * 128 + ncol * 64 + nt * 8 + qrow;
        int k  = k16 * 16 + 2 * qcol + r * 8;
        const float* wr = Wih + (size_t)gd * D_ + k;
        __half2 h2 = __floats2half2_rn(wr[0], wr[1]);
        g_wih[e2] = *(uint32_t*)&h2;
    } else {
        // x -> A-fragment image
        int e3 = e - 196608;
        if (e3 >= 524288) return;
        int lane = e3 & 31, mgroup = (e3 >> 5) & 7;
        int k16 = (e3 >> 8) & 15, cb = e3 >> 12;
        int qrow = lane >> 2, qcol = lane & 3;
        int r0 = cb * 128 + mgroup * 16 + qrow, r1 = r0 + 8;
        int kb = k16 * 16 + 2 * qcol;
        const float* x0 = x + (size_t)r0 * D_ + kb;
        const float* x1 = x + (size_t)r1 * D_ + kb;
        __half2 w0 = __floats2half2_rn(x0[0], x0[1]);
        __half2 w1 = __floats2half2_rn(x1[0], x1[1]);
        __half2 w2 = __floats2half2_rn(x0[8], x0[9]);
        __half2 w3 = __floats2half2_rn(x1[8], x1[9]);
        uint4 v;
        v.x = *(uint32_t*)&w0; v.y = *(uint32_t*)&w1;
        v.z = *(uint32_t*)&w2; v.w = *(uint32_t*)&w3;
        g_xh[e3] = v;
    }
}

// ---------------------------------------------------------------------------
// gi = x @ W_ih^T + b_ih via fp16 mma -> packed half2 output. grid (128, 6).
// ---------------------------------------------------------------------------
#define GI_WS_W 16384
#define GI_SMEM_BYTES (GI_WS_W * 4)      // 65536 B

__global__ __launch_bounds__(256) void gi_mma_kernel(
    const float* __restrict__ bih)
{
    extern __shared__ uint32_t Wst[];

    const int tid = threadIdx.x;
    const int lane = tid & 31, wid = tid >> 5;
    const int qrow = lane >> 2, qcol = lane & 3;
    const int mwarp = wid & 3;
    const int ncol  = wid >> 2;
    const int cb = blockIdx.x;
    const int ntile = blockIdx.y;

    {   // stage Wih tile: pure linear copy from fragment image
        const uint4* ws = ((const uint4*)g_wih) + ntile * 4096;
        uint4* wd = (uint4*)Wst;
#pragma unroll
        for (int j = 0; j < 16; j++) wd[tid + j * 256] = ws[tid + j * 256];
    }
    __syncthreads();

    float acc[2][8][4];
#pragma unroll
    for (int mt = 0; mt < 2; mt++)
#pragma unroll
        for (int nt = 0; nt < 8; nt++)
#pragma unroll
            for (int e = 0; e < 4; e++) acc[mt][nt][e] = 0.f;

    const uint4* xp = g_xh + (size_t)cb * 4096;
    uint4 apf[2];
    apf[0] = xp[(mwarp * 2 + 0) * 32 + lane];
    apf[1] = xp[(mwarp * 2 + 1) * 32 + lane];

#pragma unroll
    for (int k16 = 0; k16 < 16; k16++) {
        uint4 a0 = apf[0], a1 = apf[1];
        if (k16 < 15) {
            apf[0] = xp[((k16 + 1) * 8 + mwarp * 2 + 0) * 32 + lane];
            apf[1] = xp[((k16 + 1) * 8 + mwarp * 2 + 1) * 32 + lane];
        }
        const uint32_t* wb = Wst + k16 * 1024 + ncol * 512 + lane * 2;
#pragma unroll
        for (int nt = 0; nt < 8; nt++) {
            uint2 b = *(const uint2*)(wb + nt * 64);
            mma16f(acc[0][nt], (const uint32_t*)&a0, b.x, b.y);
            mma16f(acc[1][nt], (const uint32_t*)&a1, b.x, b.y);
        }
    }

#pragma unroll
    for (int nt = 0; nt < 8; nt++) {
        const int gd = ntile * 128 + ncol * 64 + nt * 8 + 2 * qcol;
        const int gw = gd >> 1;
        const float2 bv = *(const float2*)(bih + gd);
#pragma unroll
        for (int mt = 0; mt < 2; mt++)
#pragma unroll
            for (int eh = 0; eh < 2; eh++) {
                const int chain = cb * 128 + mwarp * 32 + mt * 16 + eh * 8 + qrow;
                __half2 o2 = __floats2half2_rn(acc[mt][nt][eh * 2 + 0] + bv.x,
                                               acc[mt][nt][eh * 2 + 1] + bv.y);
                g_gih[(size_t)chain * 384 + gw] = *(uint32_t*)&o2;
            }
    }
}

// ---------------------------------------------------------------------------
// Main recurrence, fp16 m16n8k16, 512 threads (16 warps: 8M x 2Ncol),
// double-buffered H, FULL half2 epilogue (f16x2 tanh, packed gi/bias).
// ---------------------------------------------------------------------------
#define HW_S   136
#define HBUF_W (128 * HW_S)             // 17408
#define WSLAB  6144
#define SMF_WS   (2 * HBUF_W)           // 34816
#define SMF_BIH2 (SMF_WS + 2 * WSLAB)   // 47104 (384 words)
#define SMF_BHH2 (SMF_BIH2 + 384)       // 47488 (384 words)
#define RNN_SMEM_BYTES ((SMF_BHH2 + 384) * 4)   // 191488 B

__global__ __launch_bounds__(512, 1) void rnn_mma_kernel(
    const float* __restrict__ bih_g,
    const float* __restrict__ bhh_g,
    float* __restrict__ out)
{
    extern __shared__ uint32_t sm[];
    uint32_t* Ws_u = sm + SMF_WS;
    __half2*  bih2 = (__half2*)(sm + SMF_BIH2);
    __half2*  bhh2 = (__half2*)(sm + SMF_BHH2);

    const int tid = threadIdx.x;
    const int lane = tid & 31, wid = tid >> 5;
    const int qrow = lane >> 2, qcol = lane & 3;
    const int mbase = (wid & 7) * 16;
    const int ncol  = wid >> 3;
    const int n0 = blockIdx.x * 128;

    for (int i = tid * 4; i < HBUF_W; i += 2048)
        *(uint4*)(sm + i) = make_uint4(0, 0, 0, 0);
    for (int i = tid; i < 384; i += 512) {
        bih2[i] = __floats2half2_rn(bih_g[2 * i], bih_g[2 * i + 1]);
        bhh2[i] = __floats2half2_rn(bhh_g[2 * i], bhh_g[2 * i + 1]);
    }

    uint4 pf[3];
    {   // slab0 -> buf0, prefetch slab1
        const uint4* s = (const uint4*)g_wh;
#pragma unroll
        for (int j = 0; j < 3; j++) pf[j] = s[tid + j * 512];
        uint4* d = (uint4*)Ws_u;
#pragma unroll
        for (int j = 0; j < 3; j++) d[tid + j * 512] = pf[j];
#pragma unroll
        for (int j = 0; j < 3; j++) pf[j] = s[1536 + tid + j * 512];
    }
    __syncthreads();

    int sc = 0;   // slab phase counter (slab = sc & 15)

    for (int t = 0; t < KS_; t++) {
        uint32_t* Hcur = sm + (t & 1) * HBUF_W;
        uint32_t* Hnxt = sm + ((t + 1) & 1) * HBUF_W;

        for (int c = 0; c < 4; c++) {
            float acc[3][4][4];
#pragma unroll
            for (int g = 0; g < 3; g++)
#pragma unroll
                for (int nt = 0; nt < 4; nt++)
#pragma unroll
                    for (int e = 0; e < 4; e++) acc[g][nt][e] = 0.f;

            for (int kq = 0; kq < 4; kq++) {
                const uint32_t* W = Ws_u + (sc & 1) * WSLAB;
                {   // commit next slab (regs -> other buffer), overlaps MMA
                    uint4* d = (uint4*)(Ws_u + ((sc + 1) & 1) * WSLAB);
#pragma unroll
                    for (int j = 0; j < 3; j++) d[tid + j * 512] = pf[j];
                }
                {   // prefetch slab sc+2
                    const uint4* s = ((const uint4*)g_wh)
                                   + (size_t)((sc + 2) & 15) * (WSLAB / 4);
#pragma unroll
                    for (int j = 0; j < 3; j++) pf[j] = s[tid + j * 512];
                }

#pragma unroll
                for (int k16m = 0; k16m < 4; k16m++) {
                    const int k16 = kq * 4 + k16m;
                    const int ko  = k16 * 8 + 2 * qcol;
                    uint32_t a[4];
                    {
                        uint2 lo = *(const uint2*)(Hcur + (mbase + qrow) * HW_S + ko);
                        uint2 hi = *(const uint2*)(Hcur + (mbase + 8 + qrow) * HW_S + ko);
                        a[0] = lo.x; a[1] = hi.x; a[2] = lo.y; a[3] = hi.y;
                    }
                    const uint32_t* wk = W + (ncol * 4 + k16m) * 768 + lane * 4;
#pragma unroll
                    for (int g = 0; g < 3; g++)
#pragma unroll
                        for (int nt2 = 0; nt2 < 2; nt2++) {
                            uint4 bv = *(const uint4*)(wk + g * 256 + nt2 * 128);
                            mma16f(acc[g][nt2 * 2 + 0], a, bv.x, bv.y);
                            mma16f(acc[g][nt2 * 2 + 1], a, bv.z, bv.w);
                        }
                }
                __syncthreads();
                sc++;
            }

            // ---- fused half2 GRU epilogue for chunk c ----
#pragma unroll
            for (int nt = 0; nt < 4; nt++) {
                const int dwg = ncol * 128 + c * 32 + nt * 8 + 2 * qcol;
                const int gw  = dwg >> 1;
                const __half2 bhr = bhh2[gw];
                const __half2 bhz = bhh2[128 + gw];
                const __half2 bhn = bhh2[256 + gw];
                const int hw = hword(dwg);
#pragma unroll
                for (int eh = 0; eh < 2; eh++) {
                    const int row   = mbase + eh * 8 + qrow;
                    const int chain = n0 + row;
                    const int lp    = (chain & (L_ - 1)) - (KS_ - 1) + t;
                    __half2 gir, giz, gin;
                    if (lp >= 0) {
                        const __half2* gp = ((const __half2*)g_gih)
                                          + (size_t)(chain - (KS_ - 1) + t) * 384 + gw;
                        gir = gp[0]; giz = gp[128]; gin = gp[256];
                    } else {
                        gir = bih2[gw]; giz = bih2[128 + gw]; gin = bih2[256 + gw];
                    }
                    const __half2 ghr = __hadd2(
                        __floats2half2_rn(acc[0][nt][eh * 2], acc[0][nt][eh * 2 + 1]), bhr);
                    const __half2 ghz = __hadd2(
                        __floats2half2_rn(acc[1][nt][eh * 2], acc[1][nt][eh * 2 + 1]), bhz);
                    const __half2 ghn = __hadd2(
                        __floats2half2_rn(acc[2][nt][eh * 2], acc[2][nt][eh * 2 + 1]), bhn);
                    const __half2 rg = sig2(__hadd2(gir, ghr));
                    const __half2 zg = sig2(__hadd2(giz, ghz));
                    const __half2 ng = tanh2(__hadd2(gin, __hmul2(rg, ghn)));
                    const __half2 ho = *(const __half2*)(Hcur + row * HW_S + hw);
                    const __half2 hv = __hfma2(zg, __hsub2(ho, ng), ng);
                    if (t == KS_ - 1) {
                        float2 o = __half22float2(hv);
                        *(float2*)(out + (size_t)chain * D_ + dwg) = o;
                    } else {
                        Hnxt[row * HW_S + hw] = *(const uint32_t*)&hv;
                    }
                }
            }
        }

        if (t < KS_ - 1) __syncthreads();   // Hnxt complete before next step reads
    }
}

// ---------------------------------------------------------------------------
// Launch: prep -> gi -> rnn
// ---------------------------------------------------------------------------
extern "C" void kernel_launch(void* const* d_in, const int* in_sizes, int n_in,
                              void* d_out, int out_size)
{
    const float* x   = (const float*)d_in[0];
    const float* Wih = (const float*)d_in[1];
    const float* Whh = (const float*)d_in[2];
    const float* bih = (const float*)d_in[3];
    const float* bhh = (const float*)d_in[4];
    float* out = (float*)d_out;

    prep_kernel<<<2816, 256>>>(x, Wih, Whh);

    cudaFuncSetAttribute(gi_mma_kernel,
                         cudaFuncAttributeMaxDynamicSharedMemorySize, GI_SMEM_BYTES);
    dim3 gi_grid(NCH_ / 128, G_ / 128);
    gi_mma_kernel<<<gi_grid, 256, GI_SMEM_BYTES>>>(bih);

    cudaFuncSetAttribute(rnn_mma_kernel,
                         cudaFuncAttributeMaxDynamicSharedMemorySize, RNN_SMEM_BYTES);
    rnn_mma_kernel<<<128, 512, RNN_SMEM_BYTES>>>(bih, bhh, out);
}